// round 13
// baseline (speedup 1.0000x reference)
#include <cuda_runtime.h>
#include <cuda_fp16.h>
#include <math.h>
#include <float.h>
#include <stdint.h>

// Problem constants
#define B_  16
#define S_  128
#define V_  40000
#define D_  768
#define H_  12
#define HD_ 64
#define F_  3072
#define L_  12
#define T_  (B_ * S_)   // 2048 tokens
#define VPAD 40064
#define QKVN 2304       // 3*D combined

typedef __half fp16;

// ---------------------------------------------------------------------------
// Scratch (__device__ globals; zero-initialized at load)
// ---------------------------------------------------------------------------
__device__ __align__(16) float g_h   [T_ * D_];
__device__ __align__(16) float g_qkv [T_ * QKVN];
__device__ __align__(16) float g_r   [T_ * D_];
__device__ __align__(16) float g_h1  [T_ * D_];

__device__ __align__(16) fp16 g_hb_hi [T_ * D_];
__device__ __align__(16) fp16 g_hb_lo [T_ * D_];
__device__ __align__(16) fp16 g_ab_hi [T_ * D_];
__device__ __align__(16) fp16 g_ab_lo [T_ * D_];
__device__ __align__(16) fp16 g_h1b_hi[T_ * D_];
__device__ __align__(16) fp16 g_h1b_lo[T_ * D_];
__device__ __align__(16) fp16 g_tb_hi [T_ * F_];
__device__ __align__(16) fp16 g_tb_lo [T_ * F_];

// Prepped weights: W^T fp16 hi/lo, [N][K] K-major
__device__ __align__(16) fp16 g_wqkv_hi[L_ * QKVN * D_];
__device__ __align__(16) fp16 g_wqkv_lo[L_ * QKVN * D_];
__device__ __align__(16) fp16 g_wo_hi [L_ * D_ * D_];
__device__ __align__(16) fp16 g_wo_lo [L_ * D_ * D_];
__device__ __align__(16) fp16 g_w1_hi [L_ * D_ * F_];
__device__ __align__(16) fp16 g_w1_lo [L_ * D_ * F_];
__device__ __align__(16) fp16 g_w2_hi [L_ * D_ * F_];
__device__ __align__(16) fp16 g_w2_lo [L_ * D_ * F_];
__device__ __align__(16) fp16 g_wout_hi[VPAD * D_];   // pad rows stay zero
__device__ __align__(16) fp16 g_wout_lo[VPAD * D_];
__device__ __align__(16) float g_bqkv[L_ * QKVN];

// ---------------------------------------------------------------------------
// Helpers
// ---------------------------------------------------------------------------
__device__ __forceinline__ float gelu_exact(float x) {
    return 0.5f * x * (1.0f + erff(x * 0.70710678118654752440f));
}
__device__ __forceinline__ uint32_t pack_h2(fp16 a, fp16 b) {
    return (uint32_t)__half_as_ushort(a) |
           ((uint32_t)__half_as_ushort(b) << 16);
}
__device__ __forceinline__ void split2(float x, fp16& h, fp16& l) {
    h = __float2half_rn(x);
    l = __float2half_rn(x - __half2float(h));
}
__device__ __forceinline__ float warp_sum(float v) {
    #pragma unroll
    for (int o = 16; o > 0; o >>= 1) v += __shfl_xor_sync(0xFFFFFFFFu, v, o);
    return v;
}
__device__ __forceinline__ uint32_t smem_u32(const void* p) {
    uint32_t a;
    asm("{ .reg .u64 t; cvta.to.shared.u64 t, %1; cvt.u32.u64 %0, t; }"
        : "=r"(a) : "l"(p));
    return a;
}
#define SWZ(off) ((off) ^ (((off) >> 3) & 0x70))

__device__ __forceinline__ void cpa16(uint32_t s, const void* g) {
    asm volatile("cp.async.cg.shared.global [%0], [%1], 16;" :: "r"(s), "l"(g));
}
#define CP_COMMIT() asm volatile("cp.async.commit_group;" ::: "memory")
#define CP_WAIT0()  asm volatile("cp.async.wait_group 0;" ::: "memory")
#define CP_WAIT1()  asm volatile("cp.async.wait_group 1;" ::: "memory")
#define CP_WAIT2()  asm volatile("cp.async.wait_group 2;" ::: "memory")

__device__ __forceinline__ void ldsm4(uint32_t (&r)[4], uint32_t addr) {
    asm volatile("ldmatrix.sync.aligned.m8n8.x4.shared.b16 {%0,%1,%2,%3}, [%4];"
        : "=r"(r[0]), "=r"(r[1]), "=r"(r[2]), "=r"(r[3]) : "r"(addr));
}
// fp16 inputs, fp32 accumulate (main product)
__device__ __forceinline__ void mma_f32(float* d, const uint32_t (&a)[4],
                                        uint32_t b0, uint32_t b1) {
    asm volatile("mma.sync.aligned.m16n8k16.row.col.f32.f16.f16.f32 "
        "{%0,%1,%2,%3}, {%4,%5,%6,%7}, {%8,%9}, {%0,%1,%2,%3};"
        : "+f"(d[0]), "+f"(d[1]), "+f"(d[2]), "+f"(d[3])
        : "r"(a[0]), "r"(a[1]), "r"(a[2]), "r"(a[3]), "r"(b0), "r"(b1));
}
// fp16 inputs, fp16 accumulate (correction products)
__device__ __forceinline__ void mma_f16(uint32_t (&d)[2], const uint32_t (&a)[4],
                                        uint32_t b0, uint32_t b1) {
    asm volatile("mma.sync.aligned.m16n8k16.row.col.f16.f16.f16.f16 "
        "{%0,%1}, {%2,%3,%4,%5}, {%6,%7}, {%0,%1};"
        : "+r"(d[0]), "+r"(d[1])
        : "r"(a[0]), "r"(a[1]), "r"(a[2]), "r"(a[3]), "r"(b0), "r"(b1));
}

// ---------------------------------------------------------------------------
// Weight prep: transpose + hi/lo split. in [K,N] -> out [N,K]
// ---------------------------------------------------------------------------
__global__ void __launch_bounds__(256) prep_w_kernel(
    const float* __restrict__ in, fp16* __restrict__ ohi, fp16* __restrict__ olo,
    int K, int N, long inBatch, int zdiv, long outL, long outZ)
{
    __shared__ float t[32][33];
    const int tx = threadIdx.x, ty = threadIdx.y;
    const int n0 = blockIdx.x * 32, k0 = blockIdx.y * 32;
    const int z = blockIdx.z;
    in += (long)z * inBatch;
    long ob = (long)(z / zdiv) * outL + (long)(z % zdiv) * outZ;
    ohi += ob; olo += ob;
    #pragma unroll
    for (int i = 0; i < 4; i++)
        t[ty + i * 8][tx] = in[(long)(k0 + ty + i * 8) * N + n0 + tx];
    __syncthreads();
    #pragma unroll
    for (int i = 0; i < 4; i++) {
        float x = t[tx][ty + i * 8];
        fp16 hi, lo; split2(x, hi, lo);
        long o = (long)(n0 + ty + i * 8) * K + k0 + tx;
        ohi[o] = hi; olo[o] = lo;
    }
}

// Merged QKV prep: one launch; z = src*(L*H) + l*H + head
__global__ void __launch_bounds__(256) prep_qkv_kernel(
    const float* __restrict__ Wq, const float* __restrict__ Wk,
    const float* __restrict__ Wv, fp16* __restrict__ ohi, fp16* __restrict__ olo)
{
    __shared__ float t[32][33];
    const int tx = threadIdx.x, ty = threadIdx.y;
    const int n0 = blockIdx.x * 32, k0 = blockIdx.y * 32;  // N=HD_, K=D_
    const int z = blockIdx.z;
    const int srcIdx = z / (L_ * H_);
    const int lh = z - srcIdx * (L_ * H_);
    const int l = lh / H_, head = lh - l * H_;
    const float* in = (srcIdx == 0 ? Wq : (srcIdx == 1 ? Wk : Wv))
                    + (long)lh * D_ * HD_;
    long ob = (long)l * QKVN * D_ + (long)srcIdx * D_ * D_ + (long)head * HD_ * D_;
    ohi += ob; olo += ob;
    #pragma unroll
    for (int i = 0; i < 4; i++)
        t[ty + i * 8][tx] = in[(long)(k0 + ty + i * 8) * HD_ + n0 + tx];
    __syncthreads();
    #pragma unroll
    for (int i = 0; i < 4; i++) {
        float x = t[tx][ty + i * 8];
        fp16 hi, lo; split2(x, hi, lo);
        long o = (long)(n0 + ty + i * 8) * D_ + k0 + tx;
        ohi[o] = hi; olo[o] = lo;
    }
}

__global__ void __launch_bounds__(256) concat_bias_kernel(
    const float* __restrict__ bq, const float* __restrict__ bk,
    const float* __restrict__ bv, float* __restrict__ out)
{
    int l = blockIdx.x;
    for (int i = threadIdx.x; i < D_; i += 256) {
        out[l * QKVN + i]           = bq[l * D_ + i];
        out[l * QKVN + D_ + i]      = bk[l * D_ + i];
        out[l * QKVN + 2 * D_ + i]  = bv[l * D_ + i];
    }
}

// ---------------------------------------------------------------------------
// HMMA GEMM v2: 4-stage cp.async pipeline, K-chunk 32, prefetch distance 3.
// Smem row = 128B = [32 k-elems hi | 32 k-elems lo], SWZ swizzled.
// Stage: [A 64x128B = 8KB][B WN x 128B]. WN=128: 24KB, WN=64: 16KB.
// WN=128: 8 warps 2x4, warp tile 32x32. WN=64: warp tile 32x16.
// TERMS=3: main f32-acc + corrections (ah*bl + al*bh) in shared f16-acc.
// TERMS=1: main product only (skips all lo-plane loads + correction mmas).
// EPI: 0 fp32 acc+bias ; 1 res+acc+bias ; 2 res+gelu(acc+bias) ; 3 fp16 hi/lo
// ---------------------------------------------------------------------------
#define MG_SMEM_N(WN) (4 * (8192 + (WN) * 128) + 1024)

template<int WN, int TERMS, int EPI, bool GUARD>
__global__ void __launch_bounds__(256) mgemm_kernel(
    const fp16* __restrict__ Ahi, const fp16* __restrict__ Alo,
    const fp16* __restrict__ Bhi, const fp16* __restrict__ Blo,
    const float* __restrict__ bias, const float* __restrict__ Res,
    float* __restrict__ C, fp16* __restrict__ Chi, fp16* __restrict__ Clo,
    int K, int N)
{
    constexpr int NLD   = WN / 64;            // B ldsm4 per k-step
    constexpr int NT    = 2 * NLD;            // n8 tiles per warp
    constexpr int BOPS  = WN / 32;            // B cp.async per thread per chunk
    constexpr int STAGE = 8192 + WN * 128;

    extern __shared__ char dsm[];
    const uint32_t sraw  = smem_u32(dsm);
    const uint32_t sbase = (sraw + 1023u) & ~1023u;

    const int tid  = threadIdx.x;
    const int lane = tid & 31;
    const int wid  = tid >> 5;
    const int row0 = blockIdx.x * 64;
    const int col0 = blockIdx.y * WN;

    // A loader: 2 ops/thread; id -> row (id>>3), sub (id&7); sub<4 hi, >=4 lo
    const fp16* Agp[2]; uint32_t sAoff[2]; bool aact[2];
    #pragma unroll
    for (int j = 0; j < 2; j++) {
        int id = tid + j * 256;
        int row = id >> 3, sub = id & 7;
        int plane = sub >> 2, koff = (sub & 3) * 8;
        Agp[j] = (plane ? Alo : Ahi) + (long)(row0 + row) * K + koff;
        sAoff[j] = SWZ((uint32_t)(row * 128 + sub * 16));
        aact[j] = (TERMS == 3) || (plane == 0);
    }
    // B loader: BOPS ops/thread
    const fp16* Bgp[BOPS]; uint32_t sBoff[BOPS]; bool bact[BOPS];
    #pragma unroll
    for (int j = 0; j < BOPS; j++) {
        int id = tid + j * 256;
        int row = id >> 3, sub = id & 7;
        int plane = sub >> 2, koff = (sub & 3) * 8;
        Bgp[j] = (plane ? Blo : Bhi) + (long)(col0 + row) * K + koff;
        sBoff[j] = SWZ((uint32_t)(row * 128 + sub * 16));
        bact[j] = (TERMS == 3) || (plane == 0);
    }

#define LOAD_CHUNK(sb, ko) do {                                         \
        _Pragma("unroll")                                               \
        for (int jj = 0; jj < 2; jj++)                                  \
            if (aact[jj]) cpa16((sb) + sAoff[jj], Agp[jj] + (ko));      \
        _Pragma("unroll")                                               \
        for (int jj = 0; jj < BOPS; jj++)                               \
            if (bact[jj]) cpa16((sb) + 8192 + sBoff[jj], Bgp[jj] + (ko)); \
        CP_COMMIT();                                                    \
    } while (0)

    float acc[2][NT][4];
    #pragma unroll
    for (int i = 0; i < 2; i++)
        #pragma unroll
        for (int j = 0; j < NT; j++)
            #pragma unroll
            for (int c = 0; c < 4; c++) acc[i][j][c] = 0.f;
    uint32_t hacc[2][NT][2];
    #pragma unroll
    for (int i = 0; i < 2; i++)
        #pragma unroll
        for (int j = 0; j < NT; j++) { hacc[i][j][0] = 0u; hacc[i][j][1] = 0u; }

    const int m0w = (wid & 1) * 32;
    const int n0w = (wid >> 1) * (WN / 4);
    const uint32_t a_off0 = (uint32_t)((m0w + (lane & 15)) * 128 + ((lane >> 4) * 16));
    const uint32_t b_off0 = (uint32_t)((n0w + ((lane >> 4) * 8) + (lane & 7)) * 128
                                       + (((lane >> 3) & 1) * 16));

    const int nch = K / 32;   // K >= 768 -> nch >= 24

    // prologue: chunks 0..2 into stages 0..2 (3 groups in flight)
    LOAD_CHUNK(sbase + 0 * STAGE, 0);
    LOAD_CHUNK(sbase + 1 * STAGE, 32);
    LOAD_CHUNK(sbase + 2 * STAGE, 64);

    for (int ch = 0; ch < nch; ch++) {
        const int rem = nch - 1 - ch;
        if (rem >= 2)      { CP_WAIT2(); }
        else if (rem == 1) { CP_WAIT1(); }
        else               { CP_WAIT0(); }
        __syncthreads();
        if (ch + 3 < nch)
            LOAD_CHUNK(sbase + ((ch + 3) & 3) * STAGE, (ch + 3) * 32);

        const uint32_t sA = sbase + (ch & 3) * STAGE;
        const uint32_t sB = sA + 8192;

        #pragma unroll
        for (int ks = 0; ks < 2; ks++) {
            const uint32_t kb = ks * 32;
            uint32_t ah[2][4], bh[NLD][4];
            ldsm4(ah[0], sA + SWZ(a_off0 + kb));
            ldsm4(ah[1], sA + SWZ(a_off0 + 2048 + kb));
            #pragma unroll
            for (int np = 0; np < NLD; np++)
                ldsm4(bh[np], sB + SWZ(b_off0 + np * 2048 + kb));
            if (TERMS == 3) {
                uint32_t al[2][4], bl[NLD][4];
                ldsm4(al[0], sA + SWZ(a_off0 + 64 + kb));
                ldsm4(al[1], sA + SWZ(a_off0 + 2048 + 64 + kb));
                #pragma unroll
                for (int np = 0; np < NLD; np++)
                    ldsm4(bl[np], sB + SWZ(b_off0 + np * 2048 + 64 + kb));
                #pragma unroll
                for (int mt = 0; mt < 2; mt++)
                    #pragma unroll
                    for (int np = 0; np < NLD; np++) {
                        mma_f32(acc[mt][2 * np],     ah[mt], bh[np][0], bh[np][1]);
                        mma_f32(acc[mt][2 * np + 1], ah[mt], bh[np][2], bh[np][3]);
                        mma_f16(hacc[mt][2 * np],     ah[mt], bl[np][0], bl[np][1]);
                        mma_f16(hacc[mt][2 * np + 1], ah[mt], bl[np][2], bl[np][3]);
                        mma_f16(hacc[mt][2 * np],     al[mt], bh[np][0], bh[np][1]);
                        mma_f16(hacc[mt][2 * np + 1], al[mt], bh[np][2], bh[np][3]);
                    }
            } else {
                #pragma unroll
                for (int mt = 0; mt < 2; mt++)
                    #pragma unroll
                    for (int np = 0; np < NLD; np++) {
                        mma_f32(acc[mt][2 * np],     ah[mt], bh[np][0], bh[np][1]);
                        mma_f32(acc[mt][2 * np + 1], ah[mt], bh[np][2], bh[np][3]);
                    }
            }
        }
    }
#undef LOAD_CHUNK

    // Fold fp16 correction accumulators into fp32 acc
    if (TERMS == 3) {
        #pragma unroll
        for (int mt = 0; mt < 2; mt++)
            #pragma unroll
            for (int nt = 0; nt < NT; nt++) {
                float2 c0 = __half22float2(*(const __half2*)&hacc[mt][nt][0]);
                float2 c1 = __half22float2(*(const __half2*)&hacc[mt][nt][1]);
                acc[mt][nt][0] += c0.x; acc[mt][nt][1] += c0.y;
                acc[mt][nt][2] += c1.x; acc[mt][nt][3] += c1.y;
            }
    }

    // Epilogue
    #pragma unroll
    for (int mt = 0; mt < 2; mt++) {
        const int r0 = row0 + m0w + mt * 16 + (lane >> 2);
        #pragma unroll
        for (int nt = 0; nt < NT; nt++) {
            const int col = col0 + n0w + nt * 8 + (lane & 3) * 2;
            if (GUARD && col >= N) continue;
            const float* a4 = acc[mt][nt];
            float2 bv = *(const float2*)(bias + col);
            float o0x = a4[0] + bv.x, o0y = a4[1] + bv.y;
            float o1x = a4[2] + bv.x, o1y = a4[3] + bv.y;
            const long off0 = (long)r0 * N + col;
            const long off1 = (long)(r0 + 8) * N + col;
            if (EPI == 1) {
                float2 ra = *(const float2*)(Res + off0);
                float2 rb = *(const float2*)(Res + off1);
                o0x += ra.x; o0y += ra.y; o1x += rb.x; o1y += rb.y;
            } else if (EPI == 2) {
                float2 ra = *(const float2*)(Res + off0);
                float2 rb = *(const float2*)(Res + off1);
                o0x = ra.x + gelu_exact(o0x); o0y = ra.y + gelu_exact(o0y);
                o1x = rb.x + gelu_exact(o1x); o1y = rb.y + gelu_exact(o1y);
            }
            if (EPI == 3) {
                fp16 h0, l0, h1, l1;
                split2(o0x, h0, l0); split2(o0y, h1, l1);
                *(uint32_t*)(Chi + off0) = pack_h2(h0, h1);
                *(uint32_t*)(Clo + off0) = pack_h2(l0, l1);
                split2(o1x, h0, l0); split2(o1y, h1, l1);
                *(uint32_t*)(Chi + off1) = pack_h2(h0, h1);
                *(uint32_t*)(Clo + off1) = pack_h2(l0, l1);
            } else {
                *(float2*)(C + off0) = make_float2(o0x, o0y);
                *(float2*)(C + off1) = make_float2(o1x, o1y);
            }
        }
    }
}

// ---------------------------------------------------------------------------
// Embedding: h fp32 + hi/lo fp16
// ---------------------------------------------------------------------------
__global__ void __launch_bounds__(256) embed_kernel(
    const int* __restrict__ x, const float* __restrict__ bpe,
    const float* __restrict__ pe, float* __restrict__ h,
    fp16* __restrict__ hbh, fp16* __restrict__ hbl)
{
    int t = blockIdx.x;
    int s = t & (S_ - 1);
    long tok = x[t];
    const float* bp = bpe + tok * (long)D_;
    const float* pp = pe + (long)s * D_;
    long rb = (long)t * D_;
    #pragma unroll
    for (int i = 0; i < 3; i++) {
        int c = threadIdx.x + i * 256;
        float v = bp[c] + pp[c];
        h[rb + c] = v;
        fp16 hi, lo; split2(v, hi, lo);
        hbh[rb + c] = hi; hbl[rb + c] = lo;
    }
}

// ---------------------------------------------------------------------------
// Attention v2: one block per (b,h), 256 threads, ~101KB smem.
// ---------------------------------------------------------------------------
#define ATTN_SMEM ((128 * 64 + 128 * 129 + 512) * 4)

__global__ void __launch_bounds__(256) attn_kernel(
    const float* __restrict__ qkv, const int* __restrict__ ignore,
    fp16* __restrict__ ohi, fp16* __restrict__ olo)
{
    extern __shared__ float sm[];
    float* KV   = sm;                        // [128][64]
    float* P    = sm + 128 * 64;             // [128][129]
    float* redm = sm + 128 * 64 + 128 * 129; // [2][128]
    float* reds = redm + 256;                // [2][128]
    __shared__ int ig[S_];

    const int bh = blockIdx.x;
    const int b  = bh / H_;
    const int h  = bh % H_;
    const int tid  = threadIdx.x;
    const int q    = tid & 127;
    const int half = tid >> 7;
    const long qbase = (long)b * S_ * QKVN + (long)h * HD_;
    const long kbase = qbase + D_;
    const long vbase = qbase + 2 * D_;

    if (tid < S_) ig[tid] = ignore[b * S_ + tid];

    #pragma unroll
    for (int i = 0; i < 8; i++) {
        int idx = tid + i * 256;
        int row = idx >> 4;
        int c4  = idx & 15;
        *(float4*)&KV[row * 64 + c4 * 4] =
            *(const float4*)(qkv + kbase + (long)row * QKVN + c4 * 4);
    }
    float qr[64];
    #pragma unroll
    for (int i = 0; i < 16; i++)
        *(float4*)&qr[i * 4] = *(const float4*)(qkv + qbase + (long)q * QKVN + i * 4);
    __syncthreads();

    float mx = -FLT_MAX;
    const int k0 = half * 64;
    for (int kk = k0; kk < k0 + 64; kk++) {
        float s = 0.f;
        #pragma unroll
        for (int e = 0; e < 64; e += 4) {
            float4 kv = *(const float4*)&KV[kk * 64 + e];
            s = fmaf(qr[e + 0], kv.x, s);
            s = fmaf(qr[e + 1], kv.y, s);
            s = fmaf(qr[e + 2], kv.z, s);
            s = fmaf(qr[e + 3], kv.w, s);
        }
        bool allowed = (kk <= q) && (ig[kk] == 0 || kk == q);
        float val = allowed ? s * 0.125f : -FLT_MAX;
        P[q * 129 + kk] = val;
        mx = fmaxf(mx, val);
    }
    redm[half * 128 + q] = mx;
    __syncthreads();

    mx = fmaxf(redm[q], redm[128 + q]);

    #pragma unroll
    for (int i = 0; i < 8; i++) {
        int idx = tid + i * 256;
        int row = idx >> 4;
        int c4  = idx & 15;
        *(float4*)&KV[row * 64 + c4 * 4] =
            *(const float4*)(qkv + vbase + (long)row * QKVN + c4 * 4);
    }
    float sum = 0.f;
    for (int kk = k0; kk < k0 + 64; kk++) {
        float e = expf(P[q * 129 + kk] - mx);
        P[q * 129 + kk] = e;
        sum += e;
    }
    reds[half * 128 + q] = sum;
    __syncthreads();

    const float inv = 1.0f / (reds[q] + reds[128 + q]);

    const int d0 = half * 32;
    float acc[32] = {};
    for (int kk = 0; kk < S_; kk++) {
        float p = P[q * 129 + kk];
        #pragma unroll
        for (int e = 0; e < 32; e += 4) {
            float4 vv = *(const float4*)&KV[kk * 64 + d0 + e];
            acc[e + 0] = fmaf(p, vv.x, acc[e + 0]);
            acc[e + 1] = fmaf(p, vv.y, acc[e + 1]);
            acc[e + 2] = fmaf(p, vv.z, acc[e + 2]);
            acc[e + 3] = fmaf(p, vv.w, acc[e + 3]);
        }
    }
    const long obase = (long)(b * S_ + q) * D_ + (long)h * HD_ + d0;
    #pragma unroll
    for (int i = 0; i < 16; i++) {
        float v0 = acc[i * 2] * inv, v1 = acc[i * 2 + 1] * inv;
        fp16 h0, l0, h1, l1;
        split2(v0, h0, l0); split2(v1, h1, l1);
        *(uint32_t*)(ohi + obase + i * 2) = pack_h2(h0, h1);
        *(uint32_t*)(olo + obase + i * 2) = pack_h2(l0, l1);
    }
}

// ---------------------------------------------------------------------------
// LayerNorm: fp32 out + fp16 hi/lo out
// ---------------------------------------------------------------------------
__global__ void __launch_bounds__(256) ln_kernel(
    const float* __restrict__ x, const float* __restrict__ w,
    const float* __restrict__ b, float* __restrict__ out,
    fp16* __restrict__ obh, fp16* __restrict__ obl)
{
    const int row = blockIdx.x;
    const int tid = threadIdx.x;
    const float* xr = x + (long)row * D_;

    float v[3], s = 0.f, s2 = 0.f;
    #pragma unroll
    for (int i = 0; i < 3; i++) {
        v[i] = xr[tid + i * 256];
        s += v[i];
        s2 = fmaf(v[i], v[i], s2);
    }
    s  = warp_sum(s);
    s2 = warp_sum(s2);
    __shared__ float sh[16];
    int wid = tid >> 5, lane = tid & 31;
    if (lane == 0) { sh[wid] = s; sh[8 + wid] = s2; }
    __syncthreads();
    if (tid == 0) {
        float a = 0.f, a2 = 0.f;
        #pragma unroll
        for (int i = 0; i < 8; i++) { a += sh[i]; a2 += sh[8 + i]; }
        sh[0] = a; sh[1] = a2;
    }
    __syncthreads();
    float mu  = sh[0] * (1.0f / D_);
    float var = sh[1] * (1.0f / D_) - mu * mu;
    float rs  = rsqrtf(var + 1e-5f);
    long rb = (long)row * D_;
    #pragma unroll
    for (int i = 0; i < 3; i++) {
        int c = tid + i * 256;
        float o = (v[i] - mu) * rs * w[c] + b[c];
        out[rb + c] = o;
        fp16 hi, lo; split2(o, hi, lo);
        obh[rb + c] = hi; obl[rb + c] = lo;
    }
}

// ---------------------------------------------------------------------------
// Launch
// ---------------------------------------------------------------------------
extern "C" void kernel_launch(void* const* d_in, const int* in_sizes, int n_in,
                              void* d_out, int out_size)
{
    const int*   x      = (const int*)  d_in[0];
    const int*   ignore = (const int*)  d_in[1];
    const float* bpe    = (const float*)d_in[2];
    const float* pe     = (const float*)d_in[3];
    const float* Wq     = (const float*)d_in[4];
    const float* bq     = (const float*)d_in[5];
    const float* Wk     = (const float*)d_in[6];
    const float* bk     = (const float*)d_in[7];
    const float* Wv     = (const float*)d_in[8];
    const float* bv     = (const float*)d_in[9];
    const float* Wo     = (const float*)d_in[10];
    const float* bo     = (const float*)d_in[11];
    const float* W1     = (const float*)d_in[12];
    const float* b1     = (const float*)d_in[13];
    const float* W2     = (const float*)d_in[14];
    const float* b2     = (const float*)d_in[15];
    const float* ln1w   = (const float*)d_in[16];
    const float* ln1b   = (const float*)d_in[17];
    const float* ln2w   = (const float*)d_in[18];
    const float* ln2b   = (const float*)d_in[19];
    const float* Wout   = (const float*)d_in[20];
    const float* bout   = (const float*)d_in[21];
    float* out = (float*)d_out;

    cudaFuncSetAttribute(attn_kernel,
        cudaFuncAttributeMaxDynamicSharedMemorySize, ATTN_SMEM);
    cudaFuncSetAttribute(mgemm_kernel<128, 3, 0, false>,
        cudaFuncAttributeMaxDynamicSharedMemorySize, MG_SMEM_N(128));
    cudaFuncSetAttribute(mgemm_kernel<128, 3, 3, false>,
        cudaFuncAttributeMaxDynamicSharedMemorySize, MG_SMEM_N(128));
    cudaFuncSetAttribute(mgemm_kernel<64, 3, 1, false>,
        cudaFuncAttributeMaxDynamicSharedMemorySize, MG_SMEM_N(64));
    cudaFuncSetAttribute(mgemm_kernel<64, 3, 2, false>,
        cudaFuncAttributeMaxDynamicSharedMemorySize, MG_SMEM_N(64));
    cudaFuncSetAttribute(mgemm_kernel<128, 1, 0, true>,
        cudaFuncAttributeMaxDynamicSharedMemorySize, MG_SMEM_N(128));

    float *h, *qkv, *r, *h1, *bqkv;
    fp16 *hbh, *hbl, *abh, *abl, *h1bh, *h1bl, *tbh, *tbl;
    fp16 *wqkvh, *wqkvl, *woh, *wol, *w1h, *w1l, *w2h, *w2l, *wouth, *woutl;
    cudaGetSymbolAddress((void**)&h,    g_h);
    cudaGetSymbolAddress((void**)&qkv,  g_qkv);
    cudaGetSymbolAddress((void**)&r,    g_r);
    cudaGetSymbolAddress((void**)&h1,   g_h1);
    cudaGetSymbolAddress((void**)&hbh,  g_hb_hi);
    cudaGetSymbolAddress((void**)&hbl,  g_hb_lo);
    cudaGetSymbolAddress((void**)&abh,  g_ab_hi);
    cudaGetSymbolAddress((void**)&abl,  g_ab_lo);
    cudaGetSymbolAddress((void**)&h1bh, g_h1b_hi);
    cudaGetSymbolAddress((void**)&h1bl, g_h1b_lo);
    cudaGetSymbolAddress((void**)&tbh,  g_tb_hi);
    cudaGetSymbolAddress((void**)&tbl,  g_tb_lo);
    cudaGetSymbolAddress((void**)&wqkvh, g_wqkv_hi);
    cudaGetSymbolAddress((void**)&wqkvl, g_wqkv_lo);
    cudaGetSymbolAddress((void**)&woh,  g_wo_hi);
    cudaGetSymbolAddress((void**)&wol,  g_wo_lo);
    cudaGetSymbolAddress((void**)&w1h,  g_w1_hi);
    cudaGetSymbolAddress((void**)&w1l,  g_w1_lo);
    cudaGetSymbolAddress((void**)&w2h,  g_w2_hi);
    cudaGetSymbolAddress((void**)&w2l,  g_w2_lo);
    cudaGetSymbolAddress((void**)&wouth, g_wout_hi);
    cudaGetSymbolAddress((void**)&woutl, g_wout_lo);
    cudaGetSymbolAddress((void**)&bqkv, g_bqkv);

    const dim3 gQKV(T_ / 64, QKVN / 128);  // 32 x 18
    const dim3 gD64(T_ / 64, D_ / 64);     // 32 x 12 = 384 (WN=64)
    const dim3 gF  (T_ / 64, F_ / 128);    // 32 x 24
    const dim3 gV  (T_ / 64, VPAD / 128);  // 32 x 313

    dim3 pb(32, 8);
    // Launch order: layer-0 QKV GEMM is the 4th launch (= ncu capture slot).
    prep_qkv_kernel<<<dim3(2, 24, 3 * L_ * H_), pb>>>(Wq, Wk, Wv, wqkvh, wqkvl);
    concat_bias_kernel<<<L_, 256>>>(bq, bk, bv, bqkv);
    embed_kernel<<<T_, 256>>>(x, bpe, pe, h, hbh, hbl);
    mgemm_kernel<128, 3, 0, false><<<gQKV, 256, MG_SMEM_N(128)>>>(
        hbh, hbl, wqkvh, wqkvl, bqkv, nullptr, qkv, nullptr, nullptr, D_, QKVN);

    prep_w_kernel<<<dim3(24, 24, L_), pb>>>(Wo, woh, wol,
        D_, D_, (long)D_ * D_, 1, (long)D_ * D_, 0);
    prep_w_kernel<<<dim3(96, 24, L_), pb>>>(W1, w1h, w1l,
        D_, F_, (long)D_ * F_, 1, (long)D_ * F_, 0);
    prep_w_kernel<<<dim3(24, 96, L_), pb>>>(W2, w2h, w2l,
        F_, D_, (long)F_ * D_, 1, (long)F_ * D_, 0);
    prep_w_kernel<<<dim3(1250, 24, 1), pb>>>(Wout, wouth, woutl,
        D_, V_, 0, 1, 0, 0);

    for (int l = 0; l < L_; l++) {
        long wq_off = (long)l * QKVN * D_;
        long wd_off = (long)l * D_ * D_;
        long wf_off = (long)l * D_ * F_;

        if (l > 0) {
            mgemm_kernel<128, 3, 0, false><<<gQKV, 256, MG_SMEM_N(128)>>>(
                hbh, hbl, wqkvh + wq_off, wqkvl + wq_off, bqkv + (long)l * QKVN,
                nullptr, qkv, nullptr, nullptr, D_, QKVN);
        }

        attn_kernel<<<B_ * H_, 256, ATTN_SMEM>>>(qkv, ignore, abh, abl);

        // r = h + a @ Wo + bo  (WN=64)
        mgemm_kernel<64, 3, 1, false><<<gD64, 256, MG_SMEM_N(64)>>>(
            abh, abl, woh + wd_off, wol + wd_off, bo + (long)l * D_,
            h, r, nullptr, nullptr, D_, D_);
        ln_kernel<<<T_, 256>>>(r, ln1w + (long)l * D_, ln1b + (long)l * D_,
                               h1, h1bh, h1bl);
        // t = h1 @ W1 + b1 (fp16-only output)
        mgemm_kernel<128, 3, 3, false><<<gF, 256, MG_SMEM_N(128)>>>(
            h1bh, h1bl, w1h + wf_off, w1l + wf_off, b1 + (long)l * F_,
            nullptr, nullptr, tbh, tbl, D_, F_);
        // r = h1 + gelu(t @ W2 + b2)  (WN=64)
        mgemm_kernel<64, 3, 2, false><<<gD64, 256, MG_SMEM_N(64)>>>(
            tbh, tbl, w2h + wf_off, w2l + wf_off, b2 + (long)l * D_,
            h1, r, nullptr, nullptr, F_, D_);
        ln_kernel<<<T_, 256>>>(r, ln2w + (long)l * D_, ln2b + (long)l * D_,
                               h, hbh, hbl);
    }

    // logits = h @ Wout + bout (terminal GEMM: main term only)
    mgemm_kernel<128, 1, 0, true><<<gV, 256, MG_SMEM_N(128)>>>(
        hbh, hbl, wouth, woutl, bout, nullptr, out, nullptr, nullptr, D_, V_);
}

// round 14
// speedup vs baseline: 1.0178x; 1.0178x over previous
#include <cuda_runtime.h>
#include <cuda_fp16.h>
#include <math.h>
#include <float.h>
#include <stdint.h>

// Problem constants
#define B_  16
#define S_  128
#define V_  40000
#define D_  768
#define H_  12
#define HD_ 64
#define F_  3072
#define L_  12
#define T_  (B_ * S_)   // 2048 tokens
#define VPAD 40064
#define QKVN 2304       // 3*D combined

typedef __half fp16;

// ---------------------------------------------------------------------------
// Scratch (__device__ globals; zero-initialized at load)
// ---------------------------------------------------------------------------
__device__ __align__(16) float g_h   [T_ * D_];
__device__ __align__(16) float g_qkv [T_ * QKVN];
__device__ __align__(16) float g_r   [T_ * D_];
__device__ __align__(16) float g_h1  [T_ * D_];

__device__ __align__(16) fp16 g_hb_hi [T_ * D_];
__device__ __align__(16) fp16 g_hb_lo [T_ * D_];
__device__ __align__(16) fp16 g_ab_hi [T_ * D_];
__device__ __align__(16) fp16 g_ab_lo [T_ * D_];
__device__ __align__(16) fp16 g_h1b_hi[T_ * D_];
__device__ __align__(16) fp16 g_h1b_lo[T_ * D_];
__device__ __align__(16) fp16 g_tb_hi [T_ * F_];
__device__ __align__(16) fp16 g_tb_lo [T_ * F_];

// Prepped weights: W^T fp16 hi/lo, [N][K] K-major
__device__ __align__(16) fp16 g_wqkv_hi[L_ * QKVN * D_];
__device__ __align__(16) fp16 g_wqkv_lo[L_ * QKVN * D_];
__device__ __align__(16) fp16 g_wo_hi [L_ * D_ * D_];
__device__ __align__(16) fp16 g_wo_lo [L_ * D_ * D_];
__device__ __align__(16) fp16 g_w1_hi [L_ * D_ * F_];
__device__ __align__(16) fp16 g_w1_lo [L_ * D_ * F_];
__device__ __align__(16) fp16 g_w2_hi [L_ * D_ * F_];
__device__ __align__(16) fp16 g_w2_lo [L_ * D_ * F_];
__device__ __align__(16) fp16 g_wout_hi[VPAD * D_];   // pad rows stay zero
__device__ __align__(16) fp16 g_wout_lo[VPAD * D_];
__device__ __align__(16) float g_bqkv[L_ * QKVN];

// ---------------------------------------------------------------------------
// Helpers
// ---------------------------------------------------------------------------
__device__ __forceinline__ float gelu_exact(float x) {
    return 0.5f * x * (1.0f + erff(x * 0.70710678118654752440f));
}
__device__ __forceinline__ uint32_t pack_h2(fp16 a, fp16 b) {
    return (uint32_t)__half_as_ushort(a) |
           ((uint32_t)__half_as_ushort(b) << 16);
}
__device__ __forceinline__ void split2(float x, fp16& h, fp16& l) {
    h = __float2half_rn(x);
    l = __float2half_rn(x - __half2float(h));
}
__device__ __forceinline__ float warp_sum(float v) {
    #pragma unroll
    for (int o = 16; o > 0; o >>= 1) v += __shfl_xor_sync(0xFFFFFFFFu, v, o);
    return v;
}
__device__ __forceinline__ uint32_t smem_u32(const void* p) {
    uint32_t a;
    asm("{ .reg .u64 t; cvta.to.shared.u64 t, %1; cvt.u32.u64 %0, t; }"
        : "=r"(a) : "l"(p));
    return a;
}
#define SWZ(off) ((off) ^ (((off) >> 3) & 0x70))

__device__ __forceinline__ void cpa16(uint32_t s, const void* g) {
    asm volatile("cp.async.cg.shared.global [%0], [%1], 16;" :: "r"(s), "l"(g));
}
#define CP_COMMIT() asm volatile("cp.async.commit_group;" ::: "memory")
#define CP_WAIT0()  asm volatile("cp.async.wait_group 0;" ::: "memory")

__device__ __forceinline__ void ldsm4(uint32_t (&r)[4], uint32_t addr) {
    asm volatile("ldmatrix.sync.aligned.m8n8.x4.shared.b16 {%0,%1,%2,%3}, [%4];"
        : "=r"(r[0]), "=r"(r[1]), "=r"(r[2]), "=r"(r[3]) : "r"(addr));
}
// fp16 inputs, fp32 accumulate (main product)
__device__ __forceinline__ void mma_f32(float* d, const uint32_t (&a)[4],
                                        uint32_t b0, uint32_t b1) {
    asm volatile("mma.sync.aligned.m16n8k16.row.col.f32.f16.f16.f32 "
        "{%0,%1,%2,%3}, {%4,%5,%6,%7}, {%8,%9}, {%0,%1,%2,%3};"
        : "+f"(d[0]), "+f"(d[1]), "+f"(d[2]), "+f"(d[3])
        : "r"(a[0]), "r"(a[1]), "r"(a[2]), "r"(a[3]), "r"(b0), "r"(b1));
}
// fp16 inputs, fp16 accumulate (correction products)
__device__ __forceinline__ void mma_f16(uint32_t (&d)[2], const uint32_t (&a)[4],
                                        uint32_t b0, uint32_t b1) {
    asm volatile("mma.sync.aligned.m16n8k16.row.col.f16.f16.f16.f16 "
        "{%0,%1}, {%2,%3,%4,%5}, {%6,%7}, {%0,%1};"
        : "+r"(d[0]), "+r"(d[1])
        : "r"(a[0]), "r"(a[1]), "r"(a[2]), "r"(a[3]), "r"(b0), "r"(b1));
}

// ---------------------------------------------------------------------------
// Weight prep: transpose + hi/lo split. in [K,N] -> out [N,K]
// ---------------------------------------------------------------------------
__global__ void __launch_bounds__(256) prep_w_kernel(
    const float* __restrict__ in, fp16* __restrict__ ohi, fp16* __restrict__ olo,
    int K, int N, long inBatch, int zdiv, long outL, long outZ)
{
    __shared__ float t[32][33];
    const int tx = threadIdx.x, ty = threadIdx.y;
    const int n0 = blockIdx.x * 32, k0 = blockIdx.y * 32;
    const int z = blockIdx.z;
    in += (long)z * inBatch;
    long ob = (long)(z / zdiv) * outL + (long)(z % zdiv) * outZ;
    ohi += ob; olo += ob;
    #pragma unroll
    for (int i = 0; i < 4; i++)
        t[ty + i * 8][tx] = in[(long)(k0 + ty + i * 8) * N + n0 + tx];
    __syncthreads();
    #pragma unroll
    for (int i = 0; i < 4; i++) {
        float x = t[tx][ty + i * 8];
        fp16 hi, lo; split2(x, hi, lo);
        long o = (long)(n0 + ty + i * 8) * K + k0 + tx;
        ohi[o] = hi; olo[o] = lo;
    }
}

// Merged QKV prep: one launch; z = src*(L*H) + l*H + head
__global__ void __launch_bounds__(256) prep_qkv_kernel(
    const float* __restrict__ Wq, const float* __restrict__ Wk,
    const float* __restrict__ Wv, fp16* __restrict__ ohi, fp16* __restrict__ olo)
{
    __shared__ float t[32][33];
    const int tx = threadIdx.x, ty = threadIdx.y;
    const int n0 = blockIdx.x * 32, k0 = blockIdx.y * 32;  // N=HD_, K=D_
    const int z = blockIdx.z;
    const int srcIdx = z / (L_ * H_);
    const int lh = z - srcIdx * (L_ * H_);
    const int l = lh / H_, head = lh - l * H_;
    const float* in = (srcIdx == 0 ? Wq : (srcIdx == 1 ? Wk : Wv))
                    + (long)lh * D_ * HD_;
    long ob = (long)l * QKVN * D_ + (long)srcIdx * D_ * D_ + (long)head * HD_ * D_;
    ohi += ob; olo += ob;
    #pragma unroll
    for (int i = 0; i < 4; i++)
        t[ty + i * 8][tx] = in[(long)(k0 + ty + i * 8) * HD_ + n0 + tx];
    __syncthreads();
    #pragma unroll
    for (int i = 0; i < 4; i++) {
        float x = t[tx][ty + i * 8];
        fp16 hi, lo; split2(x, hi, lo);
        long o = (long)(n0 + ty + i * 8) * D_ + k0 + tx;
        ohi[o] = hi; olo[o] = lo;
    }
}

__global__ void __launch_bounds__(256) concat_bias_kernel(
    const float* __restrict__ bq, const float* __restrict__ bk,
    const float* __restrict__ bv, float* __restrict__ out)
{
    int l = blockIdx.x;
    for (int i = threadIdx.x; i < D_; i += 256) {
        out[l * QKVN + i]           = bq[l * D_ + i];
        out[l * QKVN + D_ + i]      = bk[l * D_ + i];
        out[l * QKVN + 2 * D_ + i]  = bv[l * D_ + i];
    }
}

// ---------------------------------------------------------------------------
// HMMA GEMM (R12 structure + MT param): C[MT-tile, WN-tile] = A x W + bias...
// MT=64/WN=128: 8 warps 2x4, warp tile 32x32 (QKV, W1, logits).
// MT=32/WN=64 : 8 warps 2x4, warp tile 16x16 (Wo, W2: fine wave granularity).
// TERMS=3: main ah*bh f32-acc + corrections (ah*bl + al*bh) in shared f16-acc.
// TERMS=1: main product only (terminal logits GEMM).
// K-chunk 64; double-buffered cp.async; 1 sync per chunk.
// Stage: [A_hi MT*128][A_lo MT*128][B_hi WN*128][B_lo WN*128], 128B rows, SWZ.
// EPI: 0 fp32 acc+bias ; 1 res+acc+bias ; 2 res+gelu(acc+bias) ; 3 fp16 hi/lo
// ---------------------------------------------------------------------------
#define MG_SMEM_MN(MT, WN) (2 * (2 * (MT) * 128 + 2 * (WN) * 128) + 1024)

template<int MT, int WN, int TERMS, int EPI, bool GUARD>
__global__ void __launch_bounds__(256) mgemm_kernel(
    const fp16* __restrict__ Ahi, const fp16* __restrict__ Alo,
    const fp16* __restrict__ Bhi, const fp16* __restrict__ Blo,
    const float* __restrict__ bias, const float* __restrict__ Res,
    float* __restrict__ C, fp16* __restrict__ Chi, fp16* __restrict__ Clo,
    int K, int N)
{
    constexpr int MTILES = MT / 32;           // m16 tiles per warp
    constexpr int ASTEPS = MT / 32;           // A loader 32-row groups per plane
    constexpr int NLD    = WN / 64;           // B ldsm4 per k-step
    constexpr int NT     = 2 * NLD;           // n8 tiles per warp
    constexpr int AB     = MT * 128;          // bytes per A plane
    constexpr int BB     = WN * 128;          // bytes per B plane
    constexpr int BSTEPS = WN / 32;           // B loader 32-row groups per plane
    constexpr int STAGE  = 2 * AB + 2 * BB;

    extern __shared__ char dsm[];
    const uint32_t sraw  = smem_u32(dsm);
    const uint32_t sbase = (sraw + 1023u) & ~1023u;

    const int tid  = threadIdx.x;
    const int lane = tid & 31;
    const int wid  = tid >> 5;
    const int row0 = blockIdx.x * MT;
    const int col0 = blockIdx.y * WN;

    const int lrow = tid >> 3;
    const int lsub = tid & 7;
    const fp16* Ah0 = Ahi + (long)(row0 + lrow) * K + lsub * 8;
    const fp16* Al0 = (TERMS == 3) ? Alo + (long)(row0 + lrow) * K + lsub * 8 : nullptr;
    const fp16* Bh0 = Bhi + (long)(col0 + lrow) * K + lsub * 8;
    const fp16* Bl0 = (TERMS == 3) ? Blo + (long)(col0 + lrow) * K + lsub * 8 : nullptr;
    const uint32_t soff0 = SWZ((uint32_t)(lrow * 128 + lsub * 16));
    const long rstep = 32L * K;

#define LOAD_CHUNK(sb, ko) do {                                         \
        _Pragma("unroll")                                               \
        for (int jj = 0; jj < ASTEPS; jj++) {                           \
            cpa16((sb) + soff0 + jj * 4096, Ah0 + (ko) + jj * rstep);   \
            if (TERMS == 3)                                             \
                cpa16((sb) + AB + soff0 + jj * 4096, Al0 + (ko) + jj * rstep); \
        }                                                               \
        _Pragma("unroll")                                               \
        for (int jj = 0; jj < BSTEPS; jj++) {                           \
            cpa16((sb) + 2 * AB + soff0 + jj * 4096, Bh0 + (ko) + jj * rstep); \
            if (TERMS == 3)                                             \
                cpa16((sb) + 2 * AB + BB + soff0 + jj * 4096,           \
                      Bl0 + (ko) + jj * rstep);                         \
        }                                                               \
        CP_COMMIT();                                                    \
    } while (0)

    float acc[MTILES][NT][4];
    #pragma unroll
    for (int i = 0; i < MTILES; i++)
        #pragma unroll
        for (int j = 0; j < NT; j++)
            #pragma unroll
            for (int c = 0; c < 4; c++) acc[i][j][c] = 0.f;
    uint32_t hacc[MTILES][NT][2];
    #pragma unroll
    for (int i = 0; i < MTILES; i++)
        #pragma unroll
        for (int j = 0; j < NT; j++) { hacc[i][j][0] = 0u; hacc[i][j][1] = 0u; }

    const int m0w = (wid & 1) * (MT / 2);
    const int n0w = (wid >> 1) * (WN / 4);
    const uint32_t a_off0 = (uint32_t)((m0w + (lane & 15)) * 128 + ((lane >> 4) * 16));
    const uint32_t b_off0 = (uint32_t)((n0w + ((lane >> 4) * 8) + (lane & 7)) * 128
                                       + (((lane >> 3) & 1) * 16));

    const int nch = K / 64;

    LOAD_CHUNK(sbase, 0);

    for (int ch = 0; ch < nch; ch++) {
        CP_WAIT0();
        __syncthreads();
        if (ch + 1 < nch)
            LOAD_CHUNK(sbase + ((ch + 1) & 1) * STAGE, (ch + 1) * 64);

        const uint32_t sA = sbase + (ch & 1) * STAGE;
        const uint32_t sB = sA + 2 * AB;

        #pragma unroll
        for (int ks = 0; ks < 4; ks++) {
            const uint32_t kb = ks * 32;
            uint32_t ah[MTILES][4], bh[NLD][4];
            #pragma unroll
            for (int i = 0; i < MTILES; i++)
                ldsm4(ah[i], sA + SWZ(a_off0 + i * 2048 + kb));
            #pragma unroll
            for (int np = 0; np < NLD; np++)
                ldsm4(bh[np], sB + SWZ(b_off0 + np * 2048 + kb));
            if (TERMS == 3) {
                uint32_t al[MTILES][4], bl[NLD][4];
                #pragma unroll
                for (int i = 0; i < MTILES; i++)
                    ldsm4(al[i], sA + AB + SWZ(a_off0 + i * 2048 + kb));
                #pragma unroll
                for (int np = 0; np < NLD; np++)
                    ldsm4(bl[np], sB + BB + SWZ(b_off0 + np * 2048 + kb));
                #pragma unroll
                for (int mt = 0; mt < MTILES; mt++)
                    #pragma unroll
                    for (int np = 0; np < NLD; np++) {
                        mma_f32(acc[mt][2 * np],     ah[mt], bh[np][0], bh[np][1]);
                        mma_f32(acc[mt][2 * np + 1], ah[mt], bh[np][2], bh[np][3]);
                        mma_f16(hacc[mt][2 * np],     ah[mt], bl[np][0], bl[np][1]);
                        mma_f16(hacc[mt][2 * np + 1], ah[mt], bl[np][2], bl[np][3]);
                        mma_f16(hacc[mt][2 * np],     al[mt], bh[np][0], bh[np][1]);
                        mma_f16(hacc[mt][2 * np + 1], al[mt], bh[np][2], bh[np][3]);
                    }
            } else {
                #pragma unroll
                for (int mt = 0; mt < MTILES; mt++)
                    #pragma unroll
                    for (int np = 0; np < NLD; np++) {
                        mma_f32(acc[mt][2 * np],     ah[mt], bh[np][0], bh[np][1]);
                        mma_f32(acc[mt][2 * np + 1], ah[mt], bh[np][2], bh[np][3]);
                    }
            }
        }
    }
#undef LOAD_CHUNK

    // Fold fp16 correction accumulators into fp32 acc
    if (TERMS == 3) {
        #pragma unroll
        for (int mt = 0; mt < MTILES; mt++)
            #pragma unroll
            for (int nt = 0; nt < NT; nt++) {
                float2 c0 = __half22float2(*(const __half2*)&hacc[mt][nt][0]);
                float2 c1 = __half22float2(*(const __half2*)&hacc[mt][nt][1]);
                acc[mt][nt][0] += c0.x; acc[mt][nt][1] += c0.y;
                acc[mt][nt][2] += c1.x; acc[mt][nt][3] += c1.y;
            }
    }

    // Epilogue
    #pragma unroll
    for (int mt = 0; mt < MTILES; mt++) {
        const int r0 = row0 + m0w + mt * 16 + (lane >> 2);
        #pragma unroll
        for (int nt = 0; nt < NT; nt++) {
            const int col = col0 + n0w + nt * 8 + (lane & 3) * 2;
            if (GUARD && col >= N) continue;
            const float* a4 = acc[mt][nt];
            float2 bv = *(const float2*)(bias + col);
            float o0x = a4[0] + bv.x, o0y = a4[1] + bv.y;
            float o1x = a4[2] + bv.x, o1y = a4[3] + bv.y;
            const long off0 = (long)r0 * N + col;
            const long off1 = (long)(r0 + 8) * N + col;
            if (EPI == 1) {
                float2 ra = *(const float2*)(Res + off0);
                float2 rb = *(const float2*)(Res + off1);
                o0x += ra.x; o0y += ra.y; o1x += rb.x; o1y += rb.y;
            } else if (EPI == 2) {
                float2 ra = *(const float2*)(Res + off0);
                float2 rb = *(const float2*)(Res + off1);
                o0x = ra.x + gelu_exact(o0x); o0y = ra.y + gelu_exact(o0y);
                o1x = rb.x + gelu_exact(o1x); o1y = rb.y + gelu_exact(o1y);
            }
            if (EPI == 3) {
                fp16 h0, l0, h1, l1;
                split2(o0x, h0, l0); split2(o0y, h1, l1);
                *(uint32_t*)(Chi + off0) = pack_h2(h0, h1);
                *(uint32_t*)(Clo + off0) = pack_h2(l0, l1);
                split2(o1x, h0, l0); split2(o1y, h1, l1);
                *(uint32_t*)(Chi + off1) = pack_h2(h0, h1);
                *(uint32_t*)(Clo + off1) = pack_h2(l0, l1);
            } else {
                *(float2*)(C + off0) = make_float2(o0x, o0y);
                *(float2*)(C + off1) = make_float2(o1x, o1y);
            }
        }
    }
}

// ---------------------------------------------------------------------------
// Embedding: h fp32 + hi/lo fp16
// ---------------------------------------------------------------------------
__global__ void __launch_bounds__(256) embed_kernel(
    const int* __restrict__ x, const float* __restrict__ bpe,
    const float* __restrict__ pe, float* __restrict__ h,
    fp16* __restrict__ hbh, fp16* __restrict__ hbl)
{
    int t = blockIdx.x;
    int s = t & (S_ - 1);
    long tok = x[t];
    const float* bp = bpe + tok * (long)D_;
    const float* pp = pe + (long)s * D_;
    long rb = (long)t * D_;
    #pragma unroll
    for (int i = 0; i < 3; i++) {
        int c = threadIdx.x + i * 256;
        float v = bp[c] + pp[c];
        h[rb + c] = v;
        fp16 hi, lo; split2(v, hi, lo);
        hbh[rb + c] = hi; hbl[rb + c] = lo;
    }
}

// ---------------------------------------------------------------------------
// Attention v2: one block per (b,h), 256 threads, ~101KB smem.
// ---------------------------------------------------------------------------
#define ATTN_SMEM ((128 * 64 + 128 * 129 + 512) * 4)

__global__ void __launch_bounds__(256) attn_kernel(
    const float* __restrict__ qkv, const int* __restrict__ ignore,
    fp16* __restrict__ ohi, fp16* __restrict__ olo)
{
    extern __shared__ float sm[];
    float* KV   = sm;                        // [128][64]
    float* P    = sm + 128 * 64;             // [128][129]
    float* redm = sm + 128 * 64 + 128 * 129; // [2][128]
    float* reds = redm + 256;                // [2][128]
    __shared__ int ig[S_];

    const int bh = blockIdx.x;
    const int b  = bh / H_;
    const int h  = bh % H_;
    const int tid  = threadIdx.x;
    const int q    = tid & 127;
    const int half = tid >> 7;
    const long qbase = (long)b * S_ * QKVN + (long)h * HD_;
    const long kbase = qbase + D_;
    const long vbase = qbase + 2 * D_;

    if (tid < S_) ig[tid] = ignore[b * S_ + tid];

    #pragma unroll
    for (int i = 0; i < 8; i++) {
        int idx = tid + i * 256;
        int row = idx >> 4;
        int c4  = idx & 15;
        *(float4*)&KV[row * 64 + c4 * 4] =
            *(const float4*)(qkv + kbase + (long)row * QKVN + c4 * 4);
    }
    float qr[64];
    #pragma unroll
    for (int i = 0; i < 16; i++)
        *(float4*)&qr[i * 4] = *(const float4*)(qkv + qbase + (long)q * QKVN + i * 4);
    __syncthreads();

    float mx = -FLT_MAX;
    const int k0 = half * 64;
    for (int kk = k0; kk < k0 + 64; kk++) {
        float s = 0.f;
        #pragma unroll
        for (int e = 0; e < 64; e += 4) {
            float4 kv = *(const float4*)&KV[kk * 64 + e];
            s = fmaf(qr[e + 0], kv.x, s);
            s = fmaf(qr[e + 1], kv.y, s);
            s = fmaf(qr[e + 2], kv.z, s);
            s = fmaf(qr[e + 3], kv.w, s);
        }
        bool allowed = (kk <= q) && (ig[kk] == 0 || kk == q);
        float val = allowed ? s * 0.125f : -FLT_MAX;
        P[q * 129 + kk] = val;
        mx = fmaxf(mx, val);
    }
    redm[half * 128 + q] = mx;
    __syncthreads();

    mx = fmaxf(redm[q], redm[128 + q]);

    #pragma unroll
    for (int i = 0; i < 8; i++) {
        int idx = tid + i * 256;
        int row = idx >> 4;
        int c4  = idx & 15;
        *(float4*)&KV[row * 64 + c4 * 4] =
            *(const float4*)(qkv + vbase + (long)row * QKVN + c4 * 4);
    }
    float sum = 0.f;
    for (int kk = k0; kk < k0 + 64; kk++) {
        float e = expf(P[q * 129 + kk] - mx);
        P[q * 129 + kk] = e;
        sum += e;
    }
    reds[half * 128 + q] = sum;
    __syncthreads();

    const float inv = 1.0f / (reds[q] + reds[128 + q]);

    const int d0 = half * 32;
    float acc[32] = {};
    for (int kk = 0; kk < S_; kk++) {
        float p = P[q * 129 + kk];
        #pragma unroll
        for (int e = 0; e < 32; e += 4) {
            float4 vv = *(const float4*)&KV[kk * 64 + d0 + e];
            acc[e + 0] = fmaf(p, vv.x, acc[e + 0]);
            acc[e + 1] = fmaf(p, vv.y, acc[e + 1]);
            acc[e + 2] = fmaf(p, vv.z, acc[e + 2]);
            acc[e + 3] = fmaf(p, vv.w, acc[e + 3]);
        }
    }
    const long obase = (long)(b * S_ + q) * D_ + (long)h * HD_ + d0;
    #pragma unroll
    for (int i = 0; i < 16; i++) {
        float v0 = acc[i * 2] * inv, v1 = acc[i * 2 + 1] * inv;
        fp16 h0, l0, h1, l1;
        split2(v0, h0, l0); split2(v1, h1, l1);
        *(uint32_t*)(ohi + obase + i * 2) = pack_h2(h0, h1);
        *(uint32_t*)(olo + obase + i * 2) = pack_h2(l0, l1);
    }
}

// ---------------------------------------------------------------------------
// LayerNorm: fp32 out + fp16 hi/lo out
// ---------------------------------------------------------------------------
__global__ void __launch_bounds__(256) ln_kernel(
    const float* __restrict__ x, const float* __restrict__ w,
    const float* __restrict__ b, float* __restrict__ out,
    fp16* __restrict__ obh, fp16* __restrict__ obl)
{
    const int row = blockIdx.x;
    const int tid = threadIdx.x;
    const float* xr = x + (long)row * D_;

    float v[3], s = 0.f, s2 = 0.f;
    #pragma unroll
    for (int i = 0; i < 3; i++) {
        v[i] = xr[tid + i * 256];
        s += v[i];
        s2 = fmaf(v[i], v[i], s2);
    }
    s  = warp_sum(s);
    s2 = warp_sum(s2);
    __shared__ float sh[16];
    int wid = tid >> 5, lane = tid & 31;
    if (lane == 0) { sh[wid] = s; sh[8 + wid] = s2; }
    __syncthreads();
    if (tid == 0) {
        float a = 0.f, a2 = 0.f;
        #pragma unroll
        for (int i = 0; i < 8; i++) { a += sh[i]; a2 += sh[8 + i]; }
        sh[0] = a; sh[1] = a2;
    }
    __syncthreads();
    float mu  = sh[0] * (1.0f / D_);
    float var = sh[1] * (1.0f / D_) - mu * mu;
    float rs  = rsqrtf(var + 1e-5f);
    long rb = (long)row * D_;
    #pragma unroll
    for (int i = 0; i < 3; i++) {
        int c = tid + i * 256;
        float o = (v[i] - mu) * rs * w[c] + b[c];
        out[rb + c] = o;
        fp16 hi, lo; split2(o, hi, lo);
        obh[rb + c] = hi; obl[rb + c] = lo;
    }
}

// ---------------------------------------------------------------------------
// Launch
// ---------------------------------------------------------------------------
extern "C" void kernel_launch(void* const* d_in, const int* in_sizes, int n_in,
                              void* d_out, int out_size)
{
    const int*   x      = (const int*)  d_in[0];
    const int*   ignore = (const int*)  d_in[1];
    const float* bpe    = (const float*)d_in[2];
    const float* pe     = (const float*)d_in[3];
    const float* Wq     = (const float*)d_in[4];
    const float* bq     = (const float*)d_in[5];
    const float* Wk     = (const float*)d_in[6];
    const float* bk     = (const float*)d_in[7];
    const float* Wv     = (const float*)d_in[8];
    const float* bv     = (const float*)d_in[9];
    const float* Wo     = (const float*)d_in[10];
    const float* bo     = (const float*)d_in[11];
    const float* W1     = (const float*)d_in[12];
    const float* b1     = (const float*)d_in[13];
    const float* W2     = (const float*)d_in[14];
    const float* b2     = (const float*)d_in[15];
    const float* ln1w   = (const float*)d_in[16];
    const float* ln1b   = (const float*)d_in[17];
    const float* ln2w   = (const float*)d_in[18];
    const float* ln2b   = (const float*)d_in[19];
    const float* Wout   = (const float*)d_in[20];
    const float* bout   = (const float*)d_in[21];
    float* out = (float*)d_out;

    cudaFuncSetAttribute(attn_kernel,
        cudaFuncAttributeMaxDynamicSharedMemorySize, ATTN_SMEM);
    cudaFuncSetAttribute(mgemm_kernel<64, 128, 3, 0, false>,
        cudaFuncAttributeMaxDynamicSharedMemorySize, MG_SMEM_MN(64, 128));
    cudaFuncSetAttribute(mgemm_kernel<64, 128, 3, 3, false>,
        cudaFuncAttributeMaxDynamicSharedMemorySize, MG_SMEM_MN(64, 128));
    cudaFuncSetAttribute(mgemm_kernel<32, 64, 3, 1, false>,
        cudaFuncAttributeMaxDynamicSharedMemorySize, MG_SMEM_MN(32, 64));
    cudaFuncSetAttribute(mgemm_kernel<32, 64, 3, 2, false>,
        cudaFuncAttributeMaxDynamicSharedMemorySize, MG_SMEM_MN(32, 64));
    cudaFuncSetAttribute(mgemm_kernel<64, 128, 1, 0, true>,
        cudaFuncAttributeMaxDynamicSharedMemorySize, MG_SMEM_MN(64, 128));

    float *h, *qkv, *r, *h1, *bqkv;
    fp16 *hbh, *hbl, *abh, *abl, *h1bh, *h1bl, *tbh, *tbl;
    fp16 *wqkvh, *wqkvl, *woh, *wol, *w1h, *w1l, *w2h, *w2l, *wouth, *woutl;
    cudaGetSymbolAddress((void**)&h,    g_h);
    cudaGetSymbolAddress((void**)&qkv,  g_qkv);
    cudaGetSymbolAddress((void**)&r,    g_r);
    cudaGetSymbolAddress((void**)&h1,   g_h1);
    cudaGetSymbolAddress((void**)&hbh,  g_hb_hi);
    cudaGetSymbolAddress((void**)&hbl,  g_hb_lo);
    cudaGetSymbolAddress((void**)&abh,  g_ab_hi);
    cudaGetSymbolAddress((void**)&abl,  g_ab_lo);
    cudaGetSymbolAddress((void**)&h1bh, g_h1b_hi);
    cudaGetSymbolAddress((void**)&h1bl, g_h1b_lo);
    cudaGetSymbolAddress((void**)&tbh,  g_tb_hi);
    cudaGetSymbolAddress((void**)&tbl,  g_tb_lo);
    cudaGetSymbolAddress((void**)&wqkvh, g_wqkv_hi);
    cudaGetSymbolAddress((void**)&wqkvl, g_wqkv_lo);
    cudaGetSymbolAddress((void**)&woh,  g_wo_hi);
    cudaGetSymbolAddress((void**)&wol,  g_wo_lo);
    cudaGetSymbolAddress((void**)&w1h,  g_w1_hi);
    cudaGetSymbolAddress((void**)&w1l,  g_w1_lo);
    cudaGetSymbolAddress((void**)&w2h,  g_w2_hi);
    cudaGetSymbolAddress((void**)&w2l,  g_w2_lo);
    cudaGetSymbolAddress((void**)&wouth, g_wout_hi);
    cudaGetSymbolAddress((void**)&woutl, g_wout_lo);
    cudaGetSymbolAddress((void**)&bqkv, g_bqkv);

    const dim3 gQKV(T_ / 64, QKVN / 128);  // 32 x 18 = 576
    const dim3 gD32(T_ / 32, D_ / 64);     // 64 x 12 = 768 (MT=32, WN=64)
    const dim3 gF  (T_ / 64, F_ / 128);    // 32 x 24 = 768
    const dim3 gV  (T_ / 64, VPAD / 128);  // 32 x 313

    dim3 pb(32, 8);
    // Launch order: layer-0 QKV GEMM is the 4th launch (= ncu capture slot).
    prep_qkv_kernel<<<dim3(2, 24, 3 * L_ * H_), pb>>>(Wq, Wk, Wv, wqkvh, wqkvl);
    concat_bias_kernel<<<L_, 256>>>(bq, bk, bv, bqkv);
    embed_kernel<<<T_, 256>>>(x, bpe, pe, h, hbh, hbl);
    mgemm_kernel<64, 128, 3, 0, false><<<gQKV, 256, MG_SMEM_MN(64, 128)>>>(
        hbh, hbl, wqkvh, wqkvl, bqkv, nullptr, qkv, nullptr, nullptr, D_, QKVN);

    prep_w_kernel<<<dim3(24, 24, L_), pb>>>(Wo, woh, wol,
        D_, D_, (long)D_ * D_, 1, (long)D_ * D_, 0);
    prep_w_kernel<<<dim3(96, 24, L_), pb>>>(W1, w1h, w1l,
        D_, F_, (long)D_ * F_, 1, (long)D_ * F_, 0);
    prep_w_kernel<<<dim3(24, 96, L_), pb>>>(W2, w2h, w2l,
        F_, D_, (long)F_ * D_, 1, (long)F_ * D_, 0);
    prep_w_kernel<<<dim3(1250, 24, 1), pb>>>(Wout, wouth, woutl,
        D_, V_, 0, 1, 0, 0);

    for (int l = 0; l < L_; l++) {
        long wq_off = (long)l * QKVN * D_;
        long wd_off = (long)l * D_ * D_;
        long wf_off = (long)l * D_ * F_;

        if (l > 0) {
            mgemm_kernel<64, 128, 3, 0, false><<<gQKV, 256, MG_SMEM_MN(64, 128)>>>(
                hbh, hbl, wqkvh + wq_off, wqkvl + wq_off, bqkv + (long)l * QKVN,
                nullptr, qkv, nullptr, nullptr, D_, QKVN);
        }

        attn_kernel<<<B_ * H_, 256, ATTN_SMEM>>>(qkv, ignore, abh, abl);

        // r = h + a @ Wo + bo  (MT=32, WN=64: 768 fine-grained blocks)
        mgemm_kernel<32, 64, 3, 1, false><<<gD32, 256, MG_SMEM_MN(32, 64)>>>(
            abh, abl, woh + wd_off, wol + wd_off, bo + (long)l * D_,
            h, r, nullptr, nullptr, D_, D_);
        ln_kernel<<<T_, 256>>>(r, ln1w + (long)l * D_, ln1b + (long)l * D_,
                               h1, h1bh, h1bl);
        // t = h1 @ W1 + b1 (fp16-only output)
        mgemm_kernel<64, 128, 3, 3, false><<<gF, 256, MG_SMEM_MN(64, 128)>>>(
            h1bh, h1bl, w1h + wf_off, w1l + wf_off, b1 + (long)l * F_,
            nullptr, nullptr, tbh, tbl, D_, F_);
        // r = h1 + gelu(t @ W2 + b2)  (MT=32, WN=64)
        mgemm_kernel<32, 64, 3, 2, false><<<gD32, 256, MG_SMEM_MN(32, 64)>>>(
            tbh, tbl, w2h + wf_off, w2l + wf_off, b2 + (long)l * D_,
            h1, r, nullptr, nullptr, F_, D_);
        ln_kernel<<<T_, 256>>>(r, ln2w + (long)l * D_, ln2b + (long)l * D_,
                               h, hbh, hbl);
    }

    // logits = h @ Wout + bout (terminal GEMM: main term only)
    mgemm_kernel<64, 128, 1, 0, true><<<gV, 256, MG_SMEM_MN(64, 128)>>>(
        hbh, hbl, wouth, woutl, bout, nullptr, out, nullptr, nullptr, D_, V_);
}

// round 15
// speedup vs baseline: 1.0847x; 1.0657x over previous
#include <cuda_runtime.h>
#include <cuda_fp16.h>
#include <math.h>
#include <float.h>
#include <stdint.h>

// Problem constants
#define B_  16
#define S_  128
#define V_  40000
#define D_  768
#define H_  12
#define HD_ 64
#define F_  3072
#define L_  12
#define T_  (B_ * S_)   // 2048 tokens
#define VPAD 40064
#define QKVN 2304       // 3*D combined

typedef __half fp16;

// ---------------------------------------------------------------------------
// Scratch (__device__ globals; zero-initialized at load)
// ---------------------------------------------------------------------------
__device__ __align__(16) float g_h   [T_ * D_];
__device__ __align__(16) float g_qkv [T_ * QKVN];
__device__ __align__(16) float g_r   [T_ * D_];
__device__ __align__(16) float g_h1  [T_ * D_];

__device__ __align__(16) fp16 g_hb_hi [T_ * D_];
__device__ __align__(16) fp16 g_hb_lo [T_ * D_];
__device__ __align__(16) fp16 g_ab_hi [T_ * D_];
__device__ __align__(16) fp16 g_ab_lo [T_ * D_];
__device__ __align__(16) fp16 g_h1b_hi[T_ * D_];
__device__ __align__(16) fp16 g_h1b_lo[T_ * D_];
__device__ __align__(16) fp16 g_tb_hi [T_ * F_];
__device__ __align__(16) fp16 g_tb_lo [T_ * F_];

// Prepped weights: W^T fp16 hi/lo, [N][K] K-major
__device__ __align__(16) fp16 g_wqkv_hi[L_ * QKVN * D_];
__device__ __align__(16) fp16 g_wqkv_lo[L_ * QKVN * D_];
__device__ __align__(16) fp16 g_wo_hi [L_ * D_ * D_];
__device__ __align__(16) fp16 g_wo_lo [L_ * D_ * D_];
__device__ __align__(16) fp16 g_w1_hi [L_ * D_ * F_];
__device__ __align__(16) fp16 g_w1_lo [L_ * D_ * F_];
__device__ __align__(16) fp16 g_w2_hi [L_ * D_ * F_];
__device__ __align__(16) fp16 g_w2_lo [L_ * D_ * F_];
__device__ __align__(16) fp16 g_wout_hi[VPAD * D_];   // pad rows stay zero
__device__ __align__(16) fp16 g_wout_lo[VPAD * D_];
__device__ __align__(16) float g_bqkv[L_ * QKVN];

// ---------------------------------------------------------------------------
// Helpers
// ---------------------------------------------------------------------------
__device__ __forceinline__ float gelu_exact(float x) {
    return 0.5f * x * (1.0f + erff(x * 0.70710678118654752440f));
}
__device__ __forceinline__ uint32_t pack_h2(fp16 a, fp16 b) {
    return (uint32_t)__half_as_ushort(a) |
           ((uint32_t)__half_as_ushort(b) << 16);
}
__device__ __forceinline__ void split2(float x, fp16& h, fp16& l) {
    h = __float2half_rn(x);
    l = __float2half_rn(x - __half2float(h));
}
__device__ __forceinline__ float warp_sum(float v) {
    #pragma unroll
    for (int o = 16; o > 0; o >>= 1) v += __shfl_xor_sync(0xFFFFFFFFu, v, o);
    return v;
}
__device__ __forceinline__ uint32_t smem_u32(const void* p) {
    uint32_t a;
    asm("{ .reg .u64 t; cvta.to.shared.u64 t, %1; cvt.u32.u64 %0, t; }"
        : "=r"(a) : "l"(p));
    return a;
}
#define SWZ(off) ((off) ^ (((off) >> 3) & 0x70))

__device__ __forceinline__ void cpa16(uint32_t s, const void* g) {
    asm volatile("cp.async.cg.shared.global [%0], [%1], 16;" :: "r"(s), "l"(g));
}
#define CP_COMMIT() asm volatile("cp.async.commit_group;" ::: "memory")
#define CP_WAIT0()  asm volatile("cp.async.wait_group 0;" ::: "memory")

__device__ __forceinline__ void ldsm4(uint32_t (&r)[4], uint32_t addr) {
    asm volatile("ldmatrix.sync.aligned.m8n8.x4.shared.b16 {%0,%1,%2,%3}, [%4];"
        : "=r"(r[0]), "=r"(r[1]), "=r"(r[2]), "=r"(r[3]) : "r"(addr));
}
// fp16 inputs, fp32 accumulate (main product)
__device__ __forceinline__ void mma_f32(float* d, const uint32_t (&a)[4],
                                        uint32_t b0, uint32_t b1) {
    asm volatile("mma.sync.aligned.m16n8k16.row.col.f32.f16.f16.f32 "
        "{%0,%1,%2,%3}, {%4,%5,%6,%7}, {%8,%9}, {%0,%1,%2,%3};"
        : "+f"(d[0]), "+f"(d[1]), "+f"(d[2]), "+f"(d[3])
        : "r"(a[0]), "r"(a[1]), "r"(a[2]), "r"(a[3]), "r"(b0), "r"(b1));
}
// fp16 inputs, fp16 accumulate (correction products)
__device__ __forceinline__ void mma_f16(uint32_t (&d)[2], const uint32_t (&a)[4],
                                        uint32_t b0, uint32_t b1) {
    asm volatile("mma.sync.aligned.m16n8k16.row.col.f16.f16.f16.f16 "
        "{%0,%1}, {%2,%3,%4,%5}, {%6,%7}, {%0,%1};"
        : "+r"(d[0]), "+r"(d[1])
        : "r"(a[0]), "r"(a[1]), "r"(a[2]), "r"(a[3]), "r"(b0), "r"(b1));
}

// ---------------------------------------------------------------------------
// Weight prep: transpose + hi/lo split. in [K,N] -> out [N,K]
// ---------------------------------------------------------------------------
__global__ void __launch_bounds__(256) prep_w_kernel(
    const float* __restrict__ in, fp16* __restrict__ ohi, fp16* __restrict__ olo,
    int K, int N, long inBatch, int zdiv, long outL, long outZ)
{
    __shared__ float t[32][33];
    const int tx = threadIdx.x, ty = threadIdx.y;
    const int n0 = blockIdx.x * 32, k0 = blockIdx.y * 32;
    const int z = blockIdx.z;
    in += (long)z * inBatch;
    long ob = (long)(z / zdiv) * outL + (long)(z % zdiv) * outZ;
    ohi += ob; olo += ob;
    #pragma unroll
    for (int i = 0; i < 4; i++)
        t[ty + i * 8][tx] = in[(long)(k0 + ty + i * 8) * N + n0 + tx];
    __syncthreads();
    #pragma unroll
    for (int i = 0; i < 4; i++) {
        float x = t[tx][ty + i * 8];
        fp16 hi, lo; split2(x, hi, lo);
        long o = (long)(n0 + ty + i * 8) * K + k0 + tx;
        ohi[o] = hi; olo[o] = lo;
    }
}

// Merged QKV prep: one launch; z = src*(L*H) + l*H + head
__global__ void __launch_bounds__(256) prep_qkv_kernel(
    const float* __restrict__ Wq, const float* __restrict__ Wk,
    const float* __restrict__ Wv, fp16* __restrict__ ohi, fp16* __restrict__ olo)
{
    __shared__ float t[32][33];
    const int tx = threadIdx.x, ty = threadIdx.y;
    const int n0 = blockIdx.x * 32, k0 = blockIdx.y * 32;  // N=HD_, K=D_
    const int z = blockIdx.z;
    const int srcIdx = z / (L_ * H_);
    const int lh = z - srcIdx * (L_ * H_);
    const int l = lh / H_, head = lh - l * H_;
    const float* in = (srcIdx == 0 ? Wq : (srcIdx == 1 ? Wk : Wv))
                    + (long)lh * D_ * HD_;
    long ob = (long)l * QKVN * D_ + (long)srcIdx * D_ * D_ + (long)head * HD_ * D_;
    ohi += ob; olo += ob;
    #pragma unroll
    for (int i = 0; i < 4; i++)
        t[ty + i * 8][tx] = in[(long)(k0 + ty + i * 8) * HD_ + n0 + tx];
    __syncthreads();
    #pragma unroll
    for (int i = 0; i < 4; i++) {
        float x = t[tx][ty + i * 8];
        fp16 hi, lo; split2(x, hi, lo);
        long o = (long)(n0 + ty + i * 8) * D_ + k0 + tx;
        ohi[o] = hi; olo[o] = lo;
    }
}

__global__ void __launch_bounds__(256) concat_bias_kernel(
    const float* __restrict__ bq, const float* __restrict__ bk,
    const float* __restrict__ bv, float* __restrict__ out)
{
    int l = blockIdx.x;
    for (int i = threadIdx.x; i < D_; i += 256) {
        out[l * QKVN + i]           = bq[l * D_ + i];
        out[l * QKVN + D_ + i]      = bk[l * D_ + i];
        out[l * QKVN + 2 * D_ + i]  = bv[l * D_ + i];
    }
}

// ---------------------------------------------------------------------------
// HMMA GEMM (exact R12 structure): C[64, WN-tile] = A x W + bias...
// WN=128: 8 warps 2x4, warp tile 32x32. WN=64: warp tile 32x16.
// TERMS=3: main ah*bh f32-acc + corrections (ah*bl + al*bh) in shared f16-acc.
// TERMS=1: main product only (terminal logits GEMM).
// K-chunk 64; double-buffered cp.async; 1 sync per chunk.
// Stage: [A_hi 8K][A_lo 8K][B_hi WN*128][B_lo WN*128], 128B rows, SWZ.
// EPI: 0 fp32 acc+bias ; 1 res+acc+bias ; 2 res+gelu(acc+bias) ; 3 fp16 hi/lo
// ---------------------------------------------------------------------------
#define MG_SMEM_N(WN) (2 * (16384 + 2 * (WN) * 128) + 1024)

template<int WN, int TERMS, int EPI, bool GUARD>
__global__ void __launch_bounds__(256) mgemm_kernel(
    const fp16* __restrict__ Ahi, const fp16* __restrict__ Alo,
    const fp16* __restrict__ Bhi, const fp16* __restrict__ Blo,
    const float* __restrict__ bias, const float* __restrict__ Res,
    float* __restrict__ C, fp16* __restrict__ Chi, fp16* __restrict__ Clo,
    int K, int N)
{
    constexpr int NLD    = WN / 64;           // B ldsm4 per k-step
    constexpr int NT     = 2 * NLD;           // n8 tiles per warp
    constexpr int BB     = WN * 128;          // bytes per B plane
    constexpr int BSTEPS = WN / 32;           // B loader 32-row groups
    constexpr int STAGE  = 16384 + 2 * BB;

    extern __shared__ char dsm[];
    const uint32_t sraw  = smem_u32(dsm);
    const uint32_t sbase = (sraw + 1023u) & ~1023u;

    const int tid  = threadIdx.x;
    const int lane = tid & 31;
    const int wid  = tid >> 5;
    const int row0 = blockIdx.x * 64;
    const int col0 = blockIdx.y * WN;

    const int lrow = tid >> 3;
    const int lsub = tid & 7;
    const fp16* Ah0 = Ahi + (long)(row0 + lrow) * K + lsub * 8;
    const fp16* Al0 = (TERMS == 3) ? Alo + (long)(row0 + lrow) * K + lsub * 8 : nullptr;
    const fp16* Bh0 = Bhi + (long)(col0 + lrow) * K + lsub * 8;
    const fp16* Bl0 = (TERMS == 3) ? Blo + (long)(col0 + lrow) * K + lsub * 8 : nullptr;
    const uint32_t soff0 = SWZ((uint32_t)(lrow * 128 + lsub * 16));
    const long rstep = 32L * K;

#define LOAD_CHUNK(sb, ko) do {                                         \
        cpa16((sb) + soff0,                 Ah0 + (ko));                \
        cpa16((sb) + soff0 + 4096,          Ah0 + (ko) + rstep);        \
        if (TERMS == 3) {                                               \
            cpa16((sb) + 8192 + soff0,          Al0 + (ko));            \
            cpa16((sb) + 8192 + soff0 + 4096,   Al0 + (ko) + rstep);    \
        }                                                               \
        _Pragma("unroll")                                               \
        for (int jj = 0; jj < BSTEPS; jj++) {                           \
            cpa16((sb) + 16384 + soff0 + jj * 4096, Bh0 + (ko) + jj * rstep); \
            if (TERMS == 3)                                             \
                cpa16((sb) + 16384 + BB + soff0 + jj * 4096,            \
                      Bl0 + (ko) + jj * rstep);                         \
        }                                                               \
        CP_COMMIT();                                                    \
    } while (0)

    float acc[2][NT][4];
    #pragma unroll
    for (int i = 0; i < 2; i++)
        #pragma unroll
        for (int j = 0; j < NT; j++)
            #pragma unroll
            for (int c = 0; c < 4; c++) acc[i][j][c] = 0.f;
    uint32_t hacc[2][NT][2];
    #pragma unroll
    for (int i = 0; i < 2; i++)
        #pragma unroll
        for (int j = 0; j < NT; j++) { hacc[i][j][0] = 0u; hacc[i][j][1] = 0u; }

    const int m0w = (wid & 1) * 32;
    const int n0w = (wid >> 1) * (WN / 4);
    const uint32_t a_off0 = (uint32_t)((m0w + (lane & 15)) * 128 + ((lane >> 4) * 16));
    const uint32_t b_off0 = (uint32_t)((n0w + ((lane >> 4) * 8) + (lane & 7)) * 128
                                       + (((lane >> 3) & 1) * 16));

    const int nch = K / 64;

    LOAD_CHUNK(sbase, 0);

    for (int ch = 0; ch < nch; ch++) {
        CP_WAIT0();
        __syncthreads();
        if (ch + 1 < nch)
            LOAD_CHUNK(sbase + ((ch + 1) & 1) * STAGE, (ch + 1) * 64);

        const uint32_t sA = sbase + (ch & 1) * STAGE;
        const uint32_t sB = sA + 16384;

        #pragma unroll
        for (int ks = 0; ks < 4; ks++) {
            const uint32_t kb = ks * 32;
            uint32_t ah[2][4], bh[NLD][4];
            ldsm4(ah[0], sA + SWZ(a_off0 + kb));
            ldsm4(ah[1], sA + SWZ(a_off0 + 2048 + kb));
            #pragma unroll
            for (int np = 0; np < NLD; np++)
                ldsm4(bh[np], sB + SWZ(b_off0 + np * 2048 + kb));
            if (TERMS == 3) {
                uint32_t al[2][4], bl[NLD][4];
                ldsm4(al[0], sA + 8192 + SWZ(a_off0 + kb));
                ldsm4(al[1], sA + 8192 + SWZ(a_off0 + 2048 + kb));
                #pragma unroll
                for (int np = 0; np < NLD; np++)
                    ldsm4(bl[np], sB + BB + SWZ(b_off0 + np * 2048 + kb));
                #pragma unroll
                for (int mt = 0; mt < 2; mt++)
                    #pragma unroll
                    for (int np = 0; np < NLD; np++) {
                        mma_f32(acc[mt][2 * np],     ah[mt], bh[np][0], bh[np][1]);
                        mma_f32(acc[mt][2 * np + 1], ah[mt], bh[np][2], bh[np][3]);
                        mma_f16(hacc[mt][2 * np],     ah[mt], bl[np][0], bl[np][1]);
                        mma_f16(hacc[mt][2 * np + 1], ah[mt], bl[np][2], bl[np][3]);
                        mma_f16(hacc[mt][2 * np],     al[mt], bh[np][0], bh[np][1]);
                        mma_f16(hacc[mt][2 * np + 1], al[mt], bh[np][2], bh[np][3]);
                    }
            } else {
                #pragma unroll
                for (int mt = 0; mt < 2; mt++)
                    #pragma unroll
                    for (int np = 0; np < NLD; np++) {
                        mma_f32(acc[mt][2 * np],     ah[mt], bh[np][0], bh[np][1]);
                        mma_f32(acc[mt][2 * np + 1], ah[mt], bh[np][2], bh[np][3]);
                    }
            }
        }
    }
#undef LOAD_CHUNK

    // Fold fp16 correction accumulators into fp32 acc
    if (TERMS == 3) {
        #pragma unroll
        for (int mt = 0; mt < 2; mt++)
            #pragma unroll
            for (int nt = 0; nt < NT; nt++) {
                float2 c0 = __half22float2(*(const __half2*)&hacc[mt][nt][0]);
                float2 c1 = __half22float2(*(const __half2*)&hacc[mt][nt][1]);
                acc[mt][nt][0] += c0.x; acc[mt][nt][1] += c0.y;
                acc[mt][nt][2] += c1.x; acc[mt][nt][3] += c1.y;
            }
    }

    // Epilogue
    #pragma unroll
    for (int mt = 0; mt < 2; mt++) {
        const int r0 = row0 + m0w + mt * 16 + (lane >> 2);
        #pragma unroll
        for (int nt = 0; nt < NT; nt++) {
            const int col = col0 + n0w + nt * 8 + (lane & 3) * 2;
            if (GUARD && col >= N) continue;
            const float* a4 = acc[mt][nt];
            float2 bv = *(const float2*)(bias + col);
            float o0x = a4[0] + bv.x, o0y = a4[1] + bv.y;
            float o1x = a4[2] + bv.x, o1y = a4[3] + bv.y;
            const long off0 = (long)r0 * N + col;
            const long off1 = (long)(r0 + 8) * N + col;
            if (EPI == 1) {
                float2 ra = *(const float2*)(Res + off0);
                float2 rb = *(const float2*)(Res + off1);
                o0x += ra.x; o0y += ra.y; o1x += rb.x; o1y += rb.y;
            } else if (EPI == 2) {
                float2 ra = *(const float2*)(Res + off0);
                float2 rb = *(const float2*)(Res + off1);
                o0x = ra.x + gelu_exact(o0x); o0y = ra.y + gelu_exact(o0y);
                o1x = rb.x + gelu_exact(o1x); o1y = rb.y + gelu_exact(o1y);
            }
            if (EPI == 3) {
                fp16 h0, l0, h1, l1;
                split2(o0x, h0, l0); split2(o0y, h1, l1);
                *(uint32_t*)(Chi + off0) = pack_h2(h0, h1);
                *(uint32_t*)(Clo + off0) = pack_h2(l0, l1);
                split2(o1x, h0, l0); split2(o1y, h1, l1);
                *(uint32_t*)(Chi + off1) = pack_h2(h0, h1);
                *(uint32_t*)(Clo + off1) = pack_h2(l0, l1);
            } else {
                *(float2*)(C + off0) = make_float2(o0x, o0y);
                *(float2*)(C + off1) = make_float2(o1x, o1y);
            }
        }
    }
}

// ---------------------------------------------------------------------------
// Embedding: h fp32 + hi/lo fp16
// ---------------------------------------------------------------------------
__global__ void __launch_bounds__(256) embed_kernel(
    const int* __restrict__ x, const float* __restrict__ bpe,
    const float* __restrict__ pe, float* __restrict__ h,
    fp16* __restrict__ hbh, fp16* __restrict__ hbl)
{
    int t = blockIdx.x;
    int s = t & (S_ - 1);
    long tok = x[t];
    const float* bp = bpe + tok * (long)D_;
    const float* pp = pe + (long)s * D_;
    long rb = (long)t * D_;
    #pragma unroll
    for (int i = 0; i < 3; i++) {
        int c = threadIdx.x + i * 256;
        float v = bp[c] + pp[c];
        h[rb + c] = v;
        fp16 hi, lo; split2(v, hi, lo);
        hbh[rb + c] = hi; hbl[rb + c] = lo;
    }
}

// ---------------------------------------------------------------------------
// Attention v2: one block per (b,h), 256 threads, ~101KB smem.
// ---------------------------------------------------------------------------
#define ATTN_SMEM ((128 * 64 + 128 * 129 + 512) * 4)

__global__ void __launch_bounds__(256) attn_kernel(
    const float* __restrict__ qkv, const int* __restrict__ ignore,
    fp16* __restrict__ ohi, fp16* __restrict__ olo)
{
    extern __shared__ float sm[];
    float* KV   = sm;                        // [128][64]
    float* P    = sm + 128 * 64;             // [128][129]
    float* redm = sm + 128 * 64 + 128 * 129; // [2][128]
    float* reds = redm + 256;                // [2][128]
    __shared__ int ig[S_];

    const int bh = blockIdx.x;
    const int b  = bh / H_;
    const int h  = bh % H_;
    const int tid  = threadIdx.x;
    const int q    = tid & 127;
    const int half = tid >> 7;
    const long qbase = (long)b * S_ * QKVN + (long)h * HD_;
    const long kbase = qbase + D_;
    const long vbase = qbase + 2 * D_;

    if (tid < S_) ig[tid] = ignore[b * S_ + tid];

    #pragma unroll
    for (int i = 0; i < 8; i++) {
        int idx = tid + i * 256;
        int row = idx >> 4;
        int c4  = idx & 15;
        *(float4*)&KV[row * 64 + c4 * 4] =
            *(const float4*)(qkv + kbase + (long)row * QKVN + c4 * 4);
    }
    float qr[64];
    #pragma unroll
    for (int i = 0; i < 16; i++)
        *(float4*)&qr[i * 4] = *(const float4*)(qkv + qbase + (long)q * QKVN + i * 4);
    __syncthreads();

    float mx = -FLT_MAX;
    const int k0 = half * 64;
    for (int kk = k0; kk < k0 + 64; kk++) {
        float s = 0.f;
        #pragma unroll
        for (int e = 0; e < 64; e += 4) {
            float4 kv = *(const float4*)&KV[kk * 64 + e];
            s = fmaf(qr[e + 0], kv.x, s);
            s = fmaf(qr[e + 1], kv.y, s);
            s = fmaf(qr[e + 2], kv.z, s);
            s = fmaf(qr[e + 3], kv.w, s);
        }
        bool allowed = (kk <= q) && (ig[kk] == 0 || kk == q);
        float val = allowed ? s * 0.125f : -FLT_MAX;
        P[q * 129 + kk] = val;
        mx = fmaxf(mx, val);
    }
    redm[half * 128 + q] = mx;
    __syncthreads();

    mx = fmaxf(redm[q], redm[128 + q]);

    #pragma unroll
    for (int i = 0; i < 8; i++) {
        int idx = tid + i * 256;
        int row = idx >> 4;
        int c4  = idx & 15;
        *(float4*)&KV[row * 64 + c4 * 4] =
            *(const float4*)(qkv + vbase + (long)row * QKVN + c4 * 4);
    }
    float sum = 0.f;
    for (int kk = k0; kk < k0 + 64; kk++) {
        float e = expf(P[q * 129 + kk] - mx);
        P[q * 129 + kk] = e;
        sum += e;
    }
    reds[half * 128 + q] = sum;
    __syncthreads();

    const float inv = 1.0f / (reds[q] + reds[128 + q]);

    const int d0 = half * 32;
    float acc[32] = {};
    for (int kk = 0; kk < S_; kk++) {
        float p = P[q * 129 + kk];
        #pragma unroll
        for (int e = 0; e < 32; e += 4) {
            float4 vv = *(const float4*)&KV[kk * 64 + d0 + e];
            acc[e + 0] = fmaf(p, vv.x, acc[e + 0]);
            acc[e + 1] = fmaf(p, vv.y, acc[e + 1]);
            acc[e + 2] = fmaf(p, vv.z, acc[e + 2]);
            acc[e + 3] = fmaf(p, vv.w, acc[e + 3]);
        }
    }
    const long obase = (long)(b * S_ + q) * D_ + (long)h * HD_ + d0;
    #pragma unroll
    for (int i = 0; i < 16; i++) {
        float v0 = acc[i * 2] * inv, v1 = acc[i * 2 + 1] * inv;
        fp16 h0, l0, h1, l1;
        split2(v0, h0, l0); split2(v1, h1, l1);
        *(uint32_t*)(ohi + obase + i * 2) = pack_h2(h0, h1);
        *(uint32_t*)(olo + obase + i * 2) = pack_h2(l0, l1);
    }
}

// ---------------------------------------------------------------------------
// LayerNorm v2: warp-per-row, no block barriers. 8 rows per 256-thread block.
// Each lane holds 24 elems (6 float4 at cols lane*4 + i*128).
// ---------------------------------------------------------------------------
__global__ void __launch_bounds__(256) ln_kernel(
    const float* __restrict__ x, const float* __restrict__ w,
    const float* __restrict__ b, float* __restrict__ out,
    fp16* __restrict__ obh, fp16* __restrict__ obl)
{
    const int wrp  = threadIdx.x >> 5;
    const int lane = threadIdx.x & 31;
    const int row  = blockIdx.x * 8 + wrp;
    const float* xr = x + (long)row * D_;

    float v[24];
    float s = 0.f, s2 = 0.f;
    #pragma unroll
    for (int i = 0; i < 6; i++) {
        float4 t = *(const float4*)(xr + lane * 4 + i * 128);
        v[i * 4 + 0] = t.x; v[i * 4 + 1] = t.y;
        v[i * 4 + 2] = t.z; v[i * 4 + 3] = t.w;
        s += t.x + t.y + t.z + t.w;
        s2 = fmaf(t.x, t.x, s2); s2 = fmaf(t.y, t.y, s2);
        s2 = fmaf(t.z, t.z, s2); s2 = fmaf(t.w, t.w, s2);
    }
    s  = warp_sum(s);
    s2 = warp_sum(s2);
    const float mu  = s * (1.0f / D_);
    const float var = s2 * (1.0f / D_) - mu * mu;
    const float rs  = rsqrtf(var + 1e-5f);

    const long rb = (long)row * D_;
    #pragma unroll
    for (int i = 0; i < 6; i++) {
        const int c = lane * 4 + i * 128;
        float4 w4 = *(const float4*)(w + c);
        float4 b4 = *(const float4*)(b + c);
        float4 o;
        o.x = (v[i * 4 + 0] - mu) * rs * w4.x + b4.x;
        o.y = (v[i * 4 + 1] - mu) * rs * w4.y + b4.y;
        o.z = (v[i * 4 + 2] - mu) * rs * w4.z + b4.z;
        o.w = (v[i * 4 + 3] - mu) * rs * w4.w + b4.w;
        *(float4*)(out + rb + c) = o;
        fp16 h0, l0, h1, l1, h2, l2, h3, l3;
        split2(o.x, h0, l0); split2(o.y, h1, l1);
        split2(o.z, h2, l2); split2(o.w, h3, l3);
        *(uint2*)(obh + rb + c) = make_uint2(pack_h2(h0, h1), pack_h2(h2, h3));
        *(uint2*)(obl + rb + c) = make_uint2(pack_h2(l0, l1), pack_h2(l2, l3));
    }
}

// ---------------------------------------------------------------------------
// Launch
// ---------------------------------------------------------------------------
extern "C" void kernel_launch(void* const* d_in, const int* in_sizes, int n_in,
                              void* d_out, int out_size)
{
    const int*   x      = (const int*)  d_in[0];
    const int*   ignore = (const int*)  d_in[1];
    const float* bpe    = (const float*)d_in[2];
    const float* pe     = (const float*)d_in[3];
    const float* Wq     = (const float*)d_in[4];
    const float* bq     = (const float*)d_in[5];
    const float* Wk     = (const float*)d_in[6];
    const float* bk     = (const float*)d_in[7];
    const float* Wv     = (const float*)d_in[8];
    const float* bv     = (const float*)d_in[9];
    const float* Wo     = (const float*)d_in[10];
    const float* bo     = (const float*)d_in[11];
    const float* W1     = (const float*)d_in[12];
    const float* b1     = (const float*)d_in[13];
    const float* W2     = (const float*)d_in[14];
    const float* b2     = (const float*)d_in[15];
    const float* ln1w   = (const float*)d_in[16];
    const float* ln1b   = (const float*)d_in[17];
    const float* ln2w   = (const float*)d_in[18];
    const float* ln2b   = (const float*)d_in[19];
    const float* Wout   = (const float*)d_in[20];
    const float* bout   = (const float*)d_in[21];
    float* out = (float*)d_out;

    cudaFuncSetAttribute(attn_kernel,
        cudaFuncAttributeMaxDynamicSharedMemorySize, ATTN_SMEM);
    cudaFuncSetAttribute(mgemm_kernel<128, 3, 0, false>,
        cudaFuncAttributeMaxDynamicSharedMemorySize, MG_SMEM_N(128));
    cudaFuncSetAttribute(mgemm_kernel<128, 3, 3, false>,
        cudaFuncAttributeMaxDynamicSharedMemorySize, MG_SMEM_N(128));
    cudaFuncSetAttribute(mgemm_kernel<64, 3, 1, false>,
        cudaFuncAttributeMaxDynamicSharedMemorySize, MG_SMEM_N(64));
    cudaFuncSetAttribute(mgemm_kernel<64, 3, 2, false>,
        cudaFuncAttributeMaxDynamicSharedMemorySize, MG_SMEM_N(64));
    cudaFuncSetAttribute(mgemm_kernel<128, 1, 0, true>,
        cudaFuncAttributeMaxDynamicSharedMemorySize, MG_SMEM_N(128));

    float *h, *qkv, *r, *h1, *bqkv;
    fp16 *hbh, *hbl, *abh, *abl, *h1bh, *h1bl, *tbh, *tbl;
    fp16 *wqkvh, *wqkvl, *woh, *wol, *w1h, *w1l, *w2h, *w2l, *wouth, *woutl;
    cudaGetSymbolAddress((void**)&h,    g_h);
    cudaGetSymbolAddress((void**)&qkv,  g_qkv);
    cudaGetSymbolAddress((void**)&r,    g_r);
    cudaGetSymbolAddress((void**)&h1,   g_h1);
    cudaGetSymbolAddress((void**)&hbh,  g_hb_hi);
    cudaGetSymbolAddress((void**)&hbl,  g_hb_lo);
    cudaGetSymbolAddress((void**)&abh,  g_ab_hi);
    cudaGetSymbolAddress((void**)&abl,  g_ab_lo);
    cudaGetSymbolAddress((void**)&h1bh, g_h1b_hi);
    cudaGetSymbolAddress((void**)&h1bl, g_h1b_lo);
    cudaGetSymbolAddress((void**)&tbh,  g_tb_hi);
    cudaGetSymbolAddress((void**)&tbl,  g_tb_lo);
    cudaGetSymbolAddress((void**)&wqkvh, g_wqkv_hi);
    cudaGetSymbolAddress((void**)&wqkvl, g_wqkv_lo);
    cudaGetSymbolAddress((void**)&woh,  g_wo_hi);
    cudaGetSymbolAddress((void**)&wol,  g_wo_lo);
    cudaGetSymbolAddress((void**)&w1h,  g_w1_hi);
    cudaGetSymbolAddress((void**)&w1l,  g_w1_lo);
    cudaGetSymbolAddress((void**)&w2h,  g_w2_hi);
    cudaGetSymbolAddress((void**)&w2l,  g_w2_lo);
    cudaGetSymbolAddress((void**)&wouth, g_wout_hi);
    cudaGetSymbolAddress((void**)&woutl, g_wout_lo);
    cudaGetSymbolAddress((void**)&bqkv, g_bqkv);

    const dim3 gQKV(T_ / 64, QKVN / 128);  // 32 x 18
    const dim3 gD64(T_ / 64, D_ / 64);     // 32 x 12 = 384 (WN=64)
    const dim3 gF  (T_ / 64, F_ / 128);    // 32 x 24
    const dim3 gV  (T_ / 64, VPAD / 128);  // 32 x 313

    dim3 pb(32, 8);
    // Launch order: layer-0 QKV GEMM is the 4th launch (= ncu capture slot).
    prep_qkv_kernel<<<dim3(2, 24, 3 * L_ * H_), pb>>>(Wq, Wk, Wv, wqkvh, wqkvl);
    concat_bias_kernel<<<L_, 256>>>(bq, bk, bv, bqkv);
    embed_kernel<<<T_, 256>>>(x, bpe, pe, h, hbh, hbl);
    mgemm_kernel<128, 3, 0, false><<<gQKV, 256, MG_SMEM_N(128)>>>(
        hbh, hbl, wqkvh, wqkvl, bqkv, nullptr, qkv, nullptr, nullptr, D_, QKVN);

    prep_w_kernel<<<dim3(24, 24, L_), pb>>>(Wo, woh, wol,
        D_, D_, (long)D_ * D_, 1, (long)D_ * D_, 0);
    prep_w_kernel<<<dim3(96, 24, L_), pb>>>(W1, w1h, w1l,
        D_, F_, (long)D_ * F_, 1, (long)D_ * F_, 0);
    prep_w_kernel<<<dim3(24, 96, L_), pb>>>(W2, w2h, w2l,
        F_, D_, (long)F_ * D_, 1, (long)F_ * D_, 0);
    prep_w_kernel<<<dim3(1250, 24, 1), pb>>>(Wout, wouth, woutl,
        D_, V_, 0, 1, 0, 0);

    for (int l = 0; l < L_; l++) {
        long wq_off = (long)l * QKVN * D_;
        long wd_off = (long)l * D_ * D_;
        long wf_off = (long)l * D_ * F_;

        if (l > 0) {
            mgemm_kernel<128, 3, 0, false><<<gQKV, 256, MG_SMEM_N(128)>>>(
                hbh, hbl, wqkvh + wq_off, wqkvl + wq_off, bqkv + (long)l * QKVN,
                nullptr, qkv, nullptr, nullptr, D_, QKVN);
        }

        attn_kernel<<<B_ * H_, 256, ATTN_SMEM>>>(qkv, ignore, abh, abl);

        // r = h + a @ Wo + bo  (WN=64: 384 blocks)
        mgemm_kernel<64, 3, 1, false><<<gD64, 256, MG_SMEM_N(64)>>>(
            abh, abl, woh + wd_off, wol + wd_off, bo + (long)l * D_,
            h, r, nullptr, nullptr, D_, D_);
        ln_kernel<<<T_ / 8, 256>>>(r, ln1w + (long)l * D_, ln1b + (long)l * D_,
                                   h1, h1bh, h1bl);
        // t = h1 @ W1 + b1 (fp16-only output)
        mgemm_kernel<128, 3, 3, false><<<gF, 256, MG_SMEM_N(128)>>>(
            h1bh, h1bl, w1h + wf_off, w1l + wf_off, b1 + (long)l * F_,
            nullptr, nullptr, tbh, tbl, D_, F_);
        // r = h1 + gelu(t @ W2 + b2)  (WN=64)
        mgemm_kernel<64, 3, 2, false><<<gD64, 256, MG_SMEM_N(64)>>>(
            tbh, tbl, w2h + wf_off, w2l + wf_off, b2 + (long)l * D_,
            h1, r, nullptr, nullptr, F_, D_);
        ln_kernel<<<T_ / 8, 256>>>(r, ln2w + (long)l * D_, ln2b + (long)l * D_,
                                   h, hbh, hbl);
    }

    // logits = h @ Wout + bout (terminal GEMM: main term only)
    mgemm_kernel<128, 1, 0, true><<<gV, 256, MG_SMEM_N(128)>>>(
        hbh, hbl, wouth, woutl, bout, nullptr, out, nullptr, nullptr, D_, V_);
}

// round 16
// speedup vs baseline: 1.0916x; 1.0064x over previous
#include <cuda_runtime.h>
#include <cuda_fp16.h>
#include <math.h>
#include <float.h>
#include <stdint.h>

// Problem constants
#define B_  16
#define S_  128
#define V_  40000
#define D_  768
#define H_  12
#define HD_ 64
#define F_  3072
#define L_  12
#define T_  (B_ * S_)   // 2048 tokens
#define VPAD 40064
#define QKVN 2304       // 3*D combined

typedef __half fp16;

// ---------------------------------------------------------------------------
// Scratch (__device__ globals; zero-initialized at load)
// ---------------------------------------------------------------------------
__device__ __align__(16) float g_h   [T_ * D_];
__device__ __align__(16) float g_qkv [T_ * QKVN];
__device__ __align__(16) float g_h1  [T_ * D_];
__device__ __align__(16) float g_part[2 * T_ * D_];   // split-K partials

__device__ __align__(16) fp16 g_hb_hi [T_ * D_];
__device__ __align__(16) fp16 g_hb_lo [T_ * D_];
__device__ __align__(16) fp16 g_ab_hi [T_ * D_];
__device__ __align__(16) fp16 g_ab_lo [T_ * D_];
__device__ __align__(16) fp16 g_h1b_hi[T_ * D_];
__device__ __align__(16) fp16 g_h1b_lo[T_ * D_];
__device__ __align__(16) fp16 g_tb_hi [T_ * F_];
__device__ __align__(16) fp16 g_tb_lo [T_ * F_];

// Prepped weights: W^T fp16 hi/lo, [N][K] K-major
__device__ __align__(16) fp16 g_wqkv_hi[L_ * QKVN * D_];
__device__ __align__(16) fp16 g_wqkv_lo[L_ * QKVN * D_];
__device__ __align__(16) fp16 g_wo_hi [L_ * D_ * D_];
__device__ __align__(16) fp16 g_wo_lo [L_ * D_ * D_];
__device__ __align__(16) fp16 g_w1_hi [L_ * D_ * F_];
__device__ __align__(16) fp16 g_w1_lo [L_ * D_ * F_];
__device__ __align__(16) fp16 g_w2_hi [L_ * D_ * F_];
__device__ __align__(16) fp16 g_w2_lo [L_ * D_ * F_];
__device__ __align__(16) fp16 g_wout_hi[VPAD * D_];   // pad rows stay zero
__device__ __align__(16) fp16 g_wout_lo[VPAD * D_];
__device__ __align__(16) float g_bqkv[L_ * QKVN];

// ---------------------------------------------------------------------------
// Helpers
// ---------------------------------------------------------------------------
__device__ __forceinline__ float gelu_exact(float x) {
    return 0.5f * x * (1.0f + erff(x * 0.70710678118654752440f));
}
__device__ __forceinline__ uint32_t pack_h2(fp16 a, fp16 b) {
    return (uint32_t)__half_as_ushort(a) |
           ((uint32_t)__half_as_ushort(b) << 16);
}
__device__ __forceinline__ void split2(float x, fp16& h, fp16& l) {
    h = __float2half_rn(x);
    l = __float2half_rn(x - __half2float(h));
}
__device__ __forceinline__ float warp_sum(float v) {
    #pragma unroll
    for (int o = 16; o > 0; o >>= 1) v += __shfl_xor_sync(0xFFFFFFFFu, v, o);
    return v;
}
__device__ __forceinline__ uint32_t smem_u32(const void* p) {
    uint32_t a;
    asm("{ .reg .u64 t; cvta.to.shared.u64 t, %1; cvt.u32.u64 %0, t; }"
        : "=r"(a) : "l"(p));
    return a;
}
#define SWZ(off) ((off) ^ (((off) >> 3) & 0x70))

__device__ __forceinline__ void cpa16(uint32_t s, const void* g) {
    asm volatile("cp.async.cg.shared.global [%0], [%1], 16;" :: "r"(s), "l"(g));
}
#define CP_COMMIT() asm volatile("cp.async.commit_group;" ::: "memory")
#define CP_WAIT0()  asm volatile("cp.async.wait_group 0;" ::: "memory")

__device__ __forceinline__ void ldsm4(uint32_t (&r)[4], uint32_t addr) {
    asm volatile("ldmatrix.sync.aligned.m8n8.x4.shared.b16 {%0,%1,%2,%3}, [%4];"
        : "=r"(r[0]), "=r"(r[1]), "=r"(r[2]), "=r"(r[3]) : "r"(addr));
}
// fp16 inputs, fp32 accumulate (main product)
__device__ __forceinline__ void mma_f32(float* d, const uint32_t (&a)[4],
                                        uint32_t b0, uint32_t b1) {
    asm volatile("mma.sync.aligned.m16n8k16.row.col.f32.f16.f16.f32 "
        "{%0,%1,%2,%3}, {%4,%5,%6,%7}, {%8,%9}, {%0,%1,%2,%3};"
        : "+f"(d[0]), "+f"(d[1]), "+f"(d[2]), "+f"(d[3])
        : "r"(a[0]), "r"(a[1]), "r"(a[2]), "r"(a[3]), "r"(b0), "r"(b1));
}
// fp16 inputs, fp16 accumulate (correction products)
__device__ __forceinline__ void mma_f16(uint32_t (&d)[2], const uint32_t (&a)[4],
                                        uint32_t b0, uint32_t b1) {
    asm volatile("mma.sync.aligned.m16n8k16.row.col.f16.f16.f16.f16 "
        "{%0,%1}, {%2,%3,%4,%5}, {%6,%7}, {%0,%1};"
        : "+r"(d[0]), "+r"(d[1])
        : "r"(a[0]), "r"(a[1]), "r"(a[2]), "r"(a[3]), "r"(b0), "r"(b1));
}

// ---------------------------------------------------------------------------
// Weight prep: transpose + hi/lo split. in [K,N] -> out [N,K]
// ---------------------------------------------------------------------------
__global__ void __launch_bounds__(256) prep_w_kernel(
    const float* __restrict__ in, fp16* __restrict__ ohi, fp16* __restrict__ olo,
    int K, int N, long inBatch, int zdiv, long outL, long outZ)
{
    __shared__ float t[32][33];
    const int tx = threadIdx.x, ty = threadIdx.y;
    const int n0 = blockIdx.x * 32, k0 = blockIdx.y * 32;
    const int z = blockIdx.z;
    in += (long)z * inBatch;
    long ob = (long)(z / zdiv) * outL + (long)(z % zdiv) * outZ;
    ohi += ob; olo += ob;
    #pragma unroll
    for (int i = 0; i < 4; i++)
        t[ty + i * 8][tx] = in[(long)(k0 + ty + i * 8) * N + n0 + tx];
    __syncthreads();
    #pragma unroll
    for (int i = 0; i < 4; i++) {
        float x = t[tx][ty + i * 8];
        fp16 hi, lo; split2(x, hi, lo);
        long o = (long)(n0 + ty + i * 8) * K + k0 + tx;
        ohi[o] = hi; olo[o] = lo;
    }
}

// Merged QKV prep: one launch; z = src*(L*H) + l*H + head
__global__ void __launch_bounds__(256) prep_qkv_kernel(
    const float* __restrict__ Wq, const float* __restrict__ Wk,
    const float* __restrict__ Wv, fp16* __restrict__ ohi, fp16* __restrict__ olo)
{
    __shared__ float t[32][33];
    const int tx = threadIdx.x, ty = threadIdx.y;
    const int n0 = blockIdx.x * 32, k0 = blockIdx.y * 32;  // N=HD_, K=D_
    const int z = blockIdx.z;
    const int srcIdx = z / (L_ * H_);
    const int lh = z - srcIdx * (L_ * H_);
    const int l = lh / H_, head = lh - l * H_;
    const float* in = (srcIdx == 0 ? Wq : (srcIdx == 1 ? Wk : Wv))
                    + (long)lh * D_ * HD_;
    long ob = (long)l * QKVN * D_ + (long)srcIdx * D_ * D_ + (long)head * HD_ * D_;
    ohi += ob; olo += ob;
    #pragma unroll
    for (int i = 0; i < 4; i++)
        t[ty + i * 8][tx] = in[(long)(k0 + ty + i * 8) * HD_ + n0 + tx];
    __syncthreads();
    #pragma unroll
    for (int i = 0; i < 4; i++) {
        float x = t[tx][ty + i * 8];
        fp16 hi, lo; split2(x, hi, lo);
        long o = (long)(n0 + ty + i * 8) * D_ + k0 + tx;
        ohi[o] = hi; olo[o] = lo;
    }
}

__global__ void __launch_bounds__(256) concat_bias_kernel(
    const float* __restrict__ bq, const float* __restrict__ bk,
    const float* __restrict__ bv, float* __restrict__ out)
{
    int l = blockIdx.x;
    for (int i = threadIdx.x; i < D_; i += 256) {
        out[l * QKVN + i]           = bq[l * D_ + i];
        out[l * QKVN + D_ + i]      = bk[l * D_ + i];
        out[l * QKVN + 2 * D_ + i]  = bv[l * D_ + i];
    }
}

// ---------------------------------------------------------------------------
// HMMA GEMM: C[64, WN-tile] = A x W (+bias...). SPLITK: blockIdx.z picks a
// K-half; EPI=4 writes a raw fp32 partial plane (combine done downstream).
// WN=128: 8 warps 2x4, warp tile 32x32. WN=64: warp tile 32x16.
// TERMS=3: main ah*bh f32-acc + corrections (ah*bl + al*bh) in shared f16-acc.
// TERMS=1: main product only (terminal logits GEMM).
// K-chunk 64; double-buffered cp.async; 1 sync per chunk.
// EPI: 0 fp32 acc+bias ; 3 fp16 hi/lo of acc+bias ; 4 raw fp32 partial
// ---------------------------------------------------------------------------
#define MG_SMEM_N(WN) (2 * (16384 + 2 * (WN) * 128) + 1024)

template<int WN, int TERMS, int EPI, bool GUARD, int SPLITK>
__global__ void __launch_bounds__(256) mgemm_kernel(
    const fp16* __restrict__ Ahi, const fp16* __restrict__ Alo,
    const fp16* __restrict__ Bhi, const fp16* __restrict__ Blo,
    const float* __restrict__ bias,
    float* __restrict__ C, fp16* __restrict__ Chi, fp16* __restrict__ Clo,
    int K, int N)
{
    constexpr int NLD    = WN / 64;           // B ldsm4 per k-step
    constexpr int NT     = 2 * NLD;           // n8 tiles per warp
    constexpr int BB     = WN * 128;          // bytes per B plane
    constexpr int BSTEPS = WN / 32;           // B loader 32-row groups
    constexpr int STAGE  = 16384 + 2 * BB;

    extern __shared__ char dsm[];
    const uint32_t sraw  = smem_u32(dsm);
    const uint32_t sbase = (sraw + 1023u) & ~1023u;

    const int tid  = threadIdx.x;
    const int lane = tid & 31;
    const int wid  = tid >> 5;
    const int row0 = blockIdx.x * 64;
    const int col0 = blockIdx.y * WN;
    const int z    = (SPLITK > 1) ? blockIdx.z : 0;
    const int Klen = K / SPLITK;
    const int kOff = z * Klen;

    const int lrow = tid >> 3;
    const int lsub = tid & 7;
    const fp16* Ah0 = Ahi + (long)(row0 + lrow) * K + kOff + lsub * 8;
    const fp16* Al0 = (TERMS == 3) ? Alo + (long)(row0 + lrow) * K + kOff + lsub * 8 : nullptr;
    const fp16* Bh0 = Bhi + (long)(col0 + lrow) * K + kOff + lsub * 8;
    const fp16* Bl0 = (TERMS == 3) ? Blo + (long)(col0 + lrow) * K + kOff + lsub * 8 : nullptr;
    const uint32_t soff0 = SWZ((uint32_t)(lrow * 128 + lsub * 16));
    const long rstep = 32L * K;

#define LOAD_CHUNK(sb, ko) do {                                         \
        cpa16((sb) + soff0,                 Ah0 + (ko));                \
        cpa16((sb) + soff0 + 4096,          Ah0 + (ko) + rstep);        \
        if (TERMS == 3) {                                               \
            cpa16((sb) + 8192 + soff0,          Al0 + (ko));            \
            cpa16((sb) + 8192 + soff0 + 4096,   Al0 + (ko) + rstep);    \
        }                                                               \
        _Pragma("unroll")                                               \
        for (int jj = 0; jj < BSTEPS; jj++) {                           \
            cpa16((sb) + 16384 + soff0 + jj * 4096, Bh0 + (ko) + jj * rstep); \
            if (TERMS == 3)                                             \
                cpa16((sb) + 16384 + BB + soff0 + jj * 4096,            \
                      Bl0 + (ko) + jj * rstep);                         \
        }                                                               \
        CP_COMMIT();                                                    \
    } while (0)

    float acc[2][NT][4];
    #pragma unroll
    for (int i = 0; i < 2; i++)
        #pragma unroll
        for (int j = 0; j < NT; j++)
            #pragma unroll
            for (int c = 0; c < 4; c++) acc[i][j][c] = 0.f;
    uint32_t hacc[2][NT][2];
    #pragma unroll
    for (int i = 0; i < 2; i++)
        #pragma unroll
        for (int j = 0; j < NT; j++) { hacc[i][j][0] = 0u; hacc[i][j][1] = 0u; }

    const int m0w = (wid & 1) * 32;
    const int n0w = (wid >> 1) * (WN / 4);
    const uint32_t a_off0 = (uint32_t)((m0w + (lane & 15)) * 128 + ((lane >> 4) * 16));
    const uint32_t b_off0 = (uint32_t)((n0w + ((lane >> 4) * 8) + (lane & 7)) * 128
                                       + (((lane >> 3) & 1) * 16));

    const int nch = Klen / 64;

    LOAD_CHUNK(sbase, 0);

    for (int ch = 0; ch < nch; ch++) {
        CP_WAIT0();
        __syncthreads();
        if (ch + 1 < nch)
            LOAD_CHUNK(sbase + ((ch + 1) & 1) * STAGE, (ch + 1) * 64);

        const uint32_t sA = sbase + (ch & 1) * STAGE;
        const uint32_t sB = sA + 16384;

        #pragma unroll
        for (int ks = 0; ks < 4; ks++) {
            const uint32_t kb = ks * 32;
            uint32_t ah[2][4], bh[NLD][4];
            ldsm4(ah[0], sA + SWZ(a_off0 + kb));
            ldsm4(ah[1], sA + SWZ(a_off0 + 2048 + kb));
            #pragma unroll
            for (int np = 0; np < NLD; np++)
                ldsm4(bh[np], sB + SWZ(b_off0 + np * 2048 + kb));
            if (TERMS == 3) {
                uint32_t al[2][4], bl[NLD][4];
                ldsm4(al[0], sA + 8192 + SWZ(a_off0 + kb));
                ldsm4(al[1], sA + 8192 + SWZ(a_off0 + 2048 + kb));
                #pragma unroll
                for (int np = 0; np < NLD; np++)
                    ldsm4(bl[np], sB + BB + SWZ(b_off0 + np * 2048 + kb));
                #pragma unroll
                for (int mt = 0; mt < 2; mt++)
                    #pragma unroll
                    for (int np = 0; np < NLD; np++) {
                        mma_f32(acc[mt][2 * np],     ah[mt], bh[np][0], bh[np][1]);
                        mma_f32(acc[mt][2 * np + 1], ah[mt], bh[np][2], bh[np][3]);
                        mma_f16(hacc[mt][2 * np],     ah[mt], bl[np][0], bl[np][1]);
                        mma_f16(hacc[mt][2 * np + 1], ah[mt], bl[np][2], bl[np][3]);
                        mma_f16(hacc[mt][2 * np],     al[mt], bh[np][0], bh[np][1]);
                        mma_f16(hacc[mt][2 * np + 1], al[mt], bh[np][2], bh[np][3]);
                    }
            } else {
                #pragma unroll
                for (int mt = 0; mt < 2; mt++)
                    #pragma unroll
                    for (int np = 0; np < NLD; np++) {
                        mma_f32(acc[mt][2 * np],     ah[mt], bh[np][0], bh[np][1]);
                        mma_f32(acc[mt][2 * np + 1], ah[mt], bh[np][2], bh[np][3]);
                    }
            }
        }
    }
#undef LOAD_CHUNK

    // Fold fp16 correction accumulators into fp32 acc
    if (TERMS == 3) {
        #pragma unroll
        for (int mt = 0; mt < 2; mt++)
            #pragma unroll
            for (int nt = 0; nt < NT; nt++) {
                float2 c0 = __half22float2(*(const __half2*)&hacc[mt][nt][0]);
                float2 c1 = __half22float2(*(const __half2*)&hacc[mt][nt][1]);
                acc[mt][nt][0] += c0.x; acc[mt][nt][1] += c0.y;
                acc[mt][nt][2] += c1.x; acc[mt][nt][3] += c1.y;
            }
    }

    // Epilogue
    float* Cz = (EPI == 4) ? C + (long)z * ((long)T_ * N) : C;
    #pragma unroll
    for (int mt = 0; mt < 2; mt++) {
        const int r0 = row0 + m0w + mt * 16 + (lane >> 2);
        #pragma unroll
        for (int nt = 0; nt < NT; nt++) {
            const int col = col0 + n0w + nt * 8 + (lane & 3) * 2;
            if (GUARD && col >= N) continue;
            const float* a4 = acc[mt][nt];
            const long off0 = (long)r0 * N + col;
            const long off1 = (long)(r0 + 8) * N + col;
            if (EPI == 4) {
                *(float2*)(Cz + off0) = make_float2(a4[0], a4[1]);
                *(float2*)(Cz + off1) = make_float2(a4[2], a4[3]);
            } else {
                float2 bv = *(const float2*)(bias + col);
                float o0x = a4[0] + bv.x, o0y = a4[1] + bv.y;
                float o1x = a4[2] + bv.x, o1y = a4[3] + bv.y;
                if (EPI == 3) {
                    fp16 h0, l0, h1, l1;
                    split2(o0x, h0, l0); split2(o0y, h1, l1);
                    *(uint32_t*)(Chi + off0) = pack_h2(h0, h1);
                    *(uint32_t*)(Clo + off0) = pack_h2(l0, l1);
                    split2(o1x, h0, l0); split2(o1y, h1, l1);
                    *(uint32_t*)(Chi + off1) = pack_h2(h0, h1);
                    *(uint32_t*)(Clo + off1) = pack_h2(l0, l1);
                } else {
                    *(float2*)(C + off0) = make_float2(o0x, o0y);
                    *(float2*)(C + off1) = make_float2(o1x, o1y);
                }
            }
        }
    }
}

// ---------------------------------------------------------------------------
// Embedding: h fp32 + hi/lo fp16
// ---------------------------------------------------------------------------
__global__ void __launch_bounds__(256) embed_kernel(
    const int* __restrict__ x, const float* __restrict__ bpe,
    const float* __restrict__ pe, float* __restrict__ h,
    fp16* __restrict__ hbh, fp16* __restrict__ hbl)
{
    int t = blockIdx.x;
    int s = t & (S_ - 1);
    long tok = x[t];
    const float* bp = bpe + tok * (long)D_;
    const float* pp = pe + (long)s * D_;
    long rb = (long)t * D_;
    #pragma unroll
    for (int i = 0; i < 3; i++) {
        int c = threadIdx.x + i * 256;
        float v = bp[c] + pp[c];
        h[rb + c] = v;
        fp16 hi, lo; split2(v, hi, lo);
        hbh[rb + c] = hi; hbl[rb + c] = lo;
    }
}

// ---------------------------------------------------------------------------
// Attention v2: one block per (b,h), 256 threads, ~101KB smem.
// ---------------------------------------------------------------------------
#define ATTN_SMEM ((128 * 64 + 128 * 129 + 512) * 4)

__global__ void __launch_bounds__(256) attn_kernel(
    const float* __restrict__ qkv, const int* __restrict__ ignore,
    fp16* __restrict__ ohi, fp16* __restrict__ olo)
{
    extern __shared__ float sm[];
    float* KV   = sm;                        // [128][64]
    float* P    = sm + 128 * 64;             // [128][129]
    float* redm = sm + 128 * 64 + 128 * 129; // [2][128]
    float* reds = redm + 256;                // [2][128]
    __shared__ int ig[S_];

    const int bh = blockIdx.x;
    const int b  = bh / H_;
    const int h  = bh % H_;
    const int tid  = threadIdx.x;
    const int q    = tid & 127;
    const int half = tid >> 7;
    const long qbase = (long)b * S_ * QKVN + (long)h * HD_;
    const long kbase = qbase + D_;
    const long vbase = qbase + 2 * D_;

    if (tid < S_) ig[tid] = ignore[b * S_ + tid];

    #pragma unroll
    for (int i = 0; i < 8; i++) {
        int idx = tid + i * 256;
        int row = idx >> 4;
        int c4  = idx & 15;
        *(float4*)&KV[row * 64 + c4 * 4] =
            *(const float4*)(qkv + kbase + (long)row * QKVN + c4 * 4);
    }
    float qr[64];
    #pragma unroll
    for (int i = 0; i < 16; i++)
        *(float4*)&qr[i * 4] = *(const float4*)(qkv + qbase + (long)q * QKVN + i * 4);
    __syncthreads();

    float mx = -FLT_MAX;
    const int k0 = half * 64;
    for (int kk = k0; kk < k0 + 64; kk++) {
        float s = 0.f;
        #pragma unroll
        for (int e = 0; e < 64; e += 4) {
            float4 kv = *(const float4*)&KV[kk * 64 + e];
            s = fmaf(qr[e + 0], kv.x, s);
            s = fmaf(qr[e + 1], kv.y, s);
            s = fmaf(qr[e + 2], kv.z, s);
            s = fmaf(qr[e + 3], kv.w, s);
        }
        bool allowed = (kk <= q) && (ig[kk] == 0 || kk == q);
        float val = allowed ? s * 0.125f : -FLT_MAX;
        P[q * 129 + kk] = val;
        mx = fmaxf(mx, val);
    }
    redm[half * 128 + q] = mx;
    __syncthreads();

    mx = fmaxf(redm[q], redm[128 + q]);

    #pragma unroll
    for (int i = 0; i < 8; i++) {
        int idx = tid + i * 256;
        int row = idx >> 4;
        int c4  = idx & 15;
        *(float4*)&KV[row * 64 + c4 * 4] =
            *(const float4*)(qkv + vbase + (long)row * QKVN + c4 * 4);
    }
    float sum = 0.f;
    for (int kk = k0; kk < k0 + 64; kk++) {
        float e = expf(P[q * 129 + kk] - mx);
        P[q * 129 + kk] = e;
        sum += e;
    }
    reds[half * 128 + q] = sum;
    __syncthreads();

    const float inv = 1.0f / (reds[q] + reds[128 + q]);

    const int d0 = half * 32;
    float acc[32] = {};
    for (int kk = 0; kk < S_; kk++) {
        float p = P[q * 129 + kk];
        #pragma unroll
        for (int e = 0; e < 32; e += 4) {
            float4 vv = *(const float4*)&KV[kk * 64 + d0 + e];
            acc[e + 0] = fmaf(p, vv.x, acc[e + 0]);
            acc[e + 1] = fmaf(p, vv.y, acc[e + 1]);
            acc[e + 2] = fmaf(p, vv.z, acc[e + 2]);
            acc[e + 3] = fmaf(p, vv.w, acc[e + 3]);
        }
    }
    const long obase = (long)(b * S_ + q) * D_ + (long)h * HD_ + d0;
    #pragma unroll
    for (int i = 0; i < 16; i++) {
        float v0 = acc[i * 2] * inv, v1 = acc[i * 2 + 1] * inv;
        fp16 h0, l0, h1, l1;
        split2(v0, h0, l0); split2(v1, h1, l1);
        *(uint32_t*)(ohi + obase + i * 2) = pack_h2(h0, h1);
        *(uint32_t*)(olo + obase + i * 2) = pack_h2(l0, l1);
    }
}

// ---------------------------------------------------------------------------
// Combine + LayerNorm: warp-per-row, no block barriers. 8 rows/block.
// v = res + [gelu](p0 + p1 + bias); out = LN(v) (fp32 + fp16 hi/lo).
// ---------------------------------------------------------------------------
template<bool GELU>
__global__ void __launch_bounds__(256) ln_comb_kernel(
    const float* __restrict__ res, const float* __restrict__ part,
    const float* __restrict__ bias, const float* __restrict__ w,
    const float* __restrict__ b, float* __restrict__ out,
    fp16* __restrict__ obh, fp16* __restrict__ obl)
{
    const int wrp  = threadIdx.x >> 5;
    const int lane = threadIdx.x & 31;
    const int row  = blockIdx.x * 8 + wrp;
    const long rb  = (long)row * D_;
    const float* p0 = part + rb;
    const float* p1 = part + (long)T_ * D_ + rb;
    const float* rr = res + rb;

    float v[24];
    float s = 0.f, s2 = 0.f;
    #pragma unroll
    for (int i = 0; i < 6; i++) {
        const int c = lane * 4 + i * 128;
        float4 r4 = *(const float4*)(rr + c);
        float4 a4 = *(const float4*)(p0 + c);
        float4 q4 = *(const float4*)(p1 + c);
        float4 b4 = *(const float4*)(bias + c);
        float t0 = a4.x + q4.x + b4.x;
        float t1 = a4.y + q4.y + b4.y;
        float t2 = a4.z + q4.z + b4.z;
        float t3 = a4.w + q4.w + b4.w;
        float x0, x1, x2, x3;
        if (GELU) {
            x0 = r4.x + gelu_exact(t0); x1 = r4.y + gelu_exact(t1);
            x2 = r4.z + gelu_exact(t2); x3 = r4.w + gelu_exact(t3);
        } else {
            x0 = r4.x + t0; x1 = r4.y + t1;
            x2 = r4.z + t2; x3 = r4.w + t3;
        }
        v[i * 4 + 0] = x0; v[i * 4 + 1] = x1;
        v[i * 4 + 2] = x2; v[i * 4 + 3] = x3;
        s += x0 + x1 + x2 + x3;
        s2 = fmaf(x0, x0, s2); s2 = fmaf(x1, x1, s2);
        s2 = fmaf(x2, x2, s2); s2 = fmaf(x3, x3, s2);
    }
    s  = warp_sum(s);
    s2 = warp_sum(s2);
    const float mu  = s * (1.0f / D_);
    const float var = s2 * (1.0f / D_) - mu * mu;
    const float rs  = rsqrtf(var + 1e-5f);

    #pragma unroll
    for (int i = 0; i < 6; i++) {
        const int c = lane * 4 + i * 128;
        float4 w4 = *(const float4*)(w + c);
        float4 b4 = *(const float4*)(b + c);
        float4 o;
        o.x = (v[i * 4 + 0] - mu) * rs * w4.x + b4.x;
        o.y = (v[i * 4 + 1] - mu) * rs * w4.y + b4.y;
        o.z = (v[i * 4 + 2] - mu) * rs * w4.z + b4.z;
        o.w = (v[i * 4 + 3] - mu) * rs * w4.w + b4.w;
        *(float4*)(out + rb + c) = o;
        fp16 h0, l0, h1, l1, h2, l2, h3, l3;
        split2(o.x, h0, l0); split2(o.y, h1, l1);
        split2(o.z, h2, l2); split2(o.w, h3, l3);
        *(uint2*)(obh + rb + c) = make_uint2(pack_h2(h0, h1), pack_h2(h2, h3));
        *(uint2*)(obl + rb + c) = make_uint2(pack_h2(l0, l1), pack_h2(l2, l3));
    }
}

// ---------------------------------------------------------------------------
// Launch
// ---------------------------------------------------------------------------
extern "C" void kernel_launch(void* const* d_in, const int* in_sizes, int n_in,
                              void* d_out, int out_size)
{
    const int*   x      = (const int*)  d_in[0];
    const int*   ignore = (const int*)  d_in[1];
    const float* bpe    = (const float*)d_in[2];
    const float* pe     = (const float*)d_in[3];
    const float* Wq     = (const float*)d_in[4];
    const float* bq     = (const float*)d_in[5];
    const float* Wk     = (const float*)d_in[6];
    const float* bk     = (const float*)d_in[7];
    const float* Wv     = (const float*)d_in[8];
    const float* bv     = (const float*)d_in[9];
    const float* Wo     = (const float*)d_in[10];
    const float* bo     = (const float*)d_in[11];
    const float* W1     = (const float*)d_in[12];
    const float* b1     = (const float*)d_in[13];
    const float* W2     = (const float*)d_in[14];
    const float* b2     = (const float*)d_in[15];
    const float* ln1w   = (const float*)d_in[16];
    const float* ln1b   = (const float*)d_in[17];
    const float* ln2w   = (const float*)d_in[18];
    const float* ln2b   = (const float*)d_in[19];
    const float* Wout   = (const float*)d_in[20];
    const float* bout   = (const float*)d_in[21];
    float* out = (float*)d_out;

    cudaFuncSetAttribute(attn_kernel,
        cudaFuncAttributeMaxDynamicSharedMemorySize, ATTN_SMEM);
    cudaFuncSetAttribute(mgemm_kernel<128, 3, 0, false, 1>,
        cudaFuncAttributeMaxDynamicSharedMemorySize, MG_SMEM_N(128));
    cudaFuncSetAttribute(mgemm_kernel<128, 3, 3, false, 1>,
        cudaFuncAttributeMaxDynamicSharedMemorySize, MG_SMEM_N(128));
    cudaFuncSetAttribute(mgemm_kernel<64, 3, 4, false, 2>,
        cudaFuncAttributeMaxDynamicSharedMemorySize, MG_SMEM_N(64));
    cudaFuncSetAttribute(mgemm_kernel<128, 1, 0, true, 1>,
        cudaFuncAttributeMaxDynamicSharedMemorySize, MG_SMEM_N(128));

    float *h, *qkv, *h1, *part, *bqkv;
    fp16 *hbh, *hbl, *abh, *abl, *h1bh, *h1bl, *tbh, *tbl;
    fp16 *wqkvh, *wqkvl, *woh, *wol, *w1h, *w1l, *w2h, *w2l, *wouth, *woutl;
    cudaGetSymbolAddress((void**)&h,    g_h);
    cudaGetSymbolAddress((void**)&qkv,  g_qkv);
    cudaGetSymbolAddress((void**)&h1,   g_h1);
    cudaGetSymbolAddress((void**)&part, g_part);
    cudaGetSymbolAddress((void**)&hbh,  g_hb_hi);
    cudaGetSymbolAddress((void**)&hbl,  g_hb_lo);
    cudaGetSymbolAddress((void**)&abh,  g_ab_hi);
    cudaGetSymbolAddress((void**)&abl,  g_ab_lo);
    cudaGetSymbolAddress((void**)&h1bh, g_h1b_hi);
    cudaGetSymbolAddress((void**)&h1bl, g_h1b_lo);
    cudaGetSymbolAddress((void**)&tbh,  g_tb_hi);
    cudaGetSymbolAddress((void**)&tbl,  g_tb_lo);
    cudaGetSymbolAddress((void**)&wqkvh, g_wqkv_hi);
    cudaGetSymbolAddress((void**)&wqkvl, g_wqkv_lo);
    cudaGetSymbolAddress((void**)&woh,  g_wo_hi);
    cudaGetSymbolAddress((void**)&wol,  g_wo_lo);
    cudaGetSymbolAddress((void**)&w1h,  g_w1_hi);
    cudaGetSymbolAddress((void**)&w1l,  g_w1_lo);
    cudaGetSymbolAddress((void**)&w2h,  g_w2_hi);
    cudaGetSymbolAddress((void**)&w2l,  g_w2_lo);
    cudaGetSymbolAddress((void**)&wouth, g_wout_hi);
    cudaGetSymbolAddress((void**)&woutl, g_wout_lo);
    cudaGetSymbolAddress((void**)&bqkv, g_bqkv);

    const dim3 gQKV(T_ / 64, QKVN / 128);      // 32 x 18
    const dim3 gDsp(T_ / 64, D_ / 64, 2);      // 32 x 12 x 2 (split-K)
    const dim3 gF  (T_ / 64, F_ / 128);        // 32 x 24
    const dim3 gV  (T_ / 64, VPAD / 128);      // 32 x 313

    dim3 pb(32, 8);
    // Launch order: layer-0 QKV GEMM is the 4th launch (= ncu capture slot).
    prep_qkv_kernel<<<dim3(2, 24, 3 * L_ * H_), pb>>>(Wq, Wk, Wv, wqkvh, wqkvl);
    concat_bias_kernel<<<L_, 256>>>(bq, bk, bv, bqkv);
    embed_kernel<<<T_, 256>>>(x, bpe, pe, h, hbh, hbl);
    mgemm_kernel<128, 3, 0, false, 1><<<gQKV, 256, MG_SMEM_N(128)>>>(
        hbh, hbl, wqkvh, wqkvl, bqkv, qkv, nullptr, nullptr, D_, QKVN);

    prep_w_kernel<<<dim3(24, 24, L_), pb>>>(Wo, woh, wol,
        D_, D_, (long)D_ * D_, 1, (long)D_ * D_, 0);
    prep_w_kernel<<<dim3(96, 24, L_), pb>>>(W1, w1h, w1l,
        D_, F_, (long)D_ * F_, 1, (long)D_ * F_, 0);
    prep_w_kernel<<<dim3(24, 96, L_), pb>>>(W2, w2h, w2l,
        F_, D_, (long)F_ * D_, 1, (long)F_ * D_, 0);
    prep_w_kernel<<<dim3(1250, 24, 1), pb>>>(Wout, wouth, woutl,
        D_, V_, 0, 1, 0, 0);

    for (int l = 0; l < L_; l++) {
        long wq_off = (long)l * QKVN * D_;
        long wd_off = (long)l * D_ * D_;
        long wf_off = (long)l * D_ * F_;

        if (l > 0) {
            mgemm_kernel<128, 3, 0, false, 1><<<gQKV, 256, MG_SMEM_N(128)>>>(
                hbh, hbl, wqkvh + wq_off, wqkvl + wq_off, bqkv + (long)l * QKVN,
                qkv, nullptr, nullptr, D_, QKVN);
        }

        attn_kernel<<<B_ * H_, 256, ATTN_SMEM>>>(qkv, ignore, abh, abl);

        // partials = a @ Wo (split-K=2)
        mgemm_kernel<64, 3, 4, false, 2><<<gDsp, 256, MG_SMEM_N(64)>>>(
            abh, abl, woh + wd_off, wol + wd_off, nullptr,
            part, nullptr, nullptr, D_, D_);
        // h1 = LN1(h + p0 + p1 + bo)
        ln_comb_kernel<false><<<T_ / 8, 256>>>(h, part, bo + (long)l * D_,
            ln1w + (long)l * D_, ln1b + (long)l * D_, h1, h1bh, h1bl);
        // t = h1 @ W1 + b1 (fp16-only output)
        mgemm_kernel<128, 3, 3, false, 1><<<gF, 256, MG_SMEM_N(128)>>>(
            h1bh, h1bl, w1h + wf_off, w1l + wf_off, b1 + (long)l * F_,
            nullptr, tbh, tbl, D_, F_);
        // partials = t @ W2 (split-K=2 over K=3072)
        mgemm_kernel<64, 3, 4, false, 2><<<gDsp, 256, MG_SMEM_N(64)>>>(
            tbh, tbl, w2h + wf_off, w2l + wf_off, nullptr,
            part, nullptr, nullptr, F_, D_);
        // h = LN2(h1 + gelu(p0 + p1 + b2))
        ln_comb_kernel<true><<<T_ / 8, 256>>>(h1, part, b2 + (long)l * D_,
            ln2w + (long)l * D_, ln2b + (long)l * D_, h, hbh, hbl);
    }

    // logits = h @ Wout + bout (terminal GEMM: main term only)
    mgemm_kernel<128, 1, 0, true, 1><<<gV, 256, MG_SMEM_N(128)>>>(
        hbh, hbl, wouth, woutl, bout, out, nullptr, nullptr, D_, V_);
}

// round 17
// speedup vs baseline: 1.1058x; 1.0131x over previous
#include <cuda_runtime.h>
#include <cuda_fp16.h>
#include <math.h>
#include <float.h>
#include <stdint.h>

// Problem constants
#define B_  16
#define S_  128
#define V_  40000
#define D_  768
#define H_  12
#define HD_ 64
#define F_  3072
#define L_  12
#define T_  (B_ * S_)   // 2048 tokens
#define VPAD 40064
#define QKVN 2304       // 3*D combined

typedef __half fp16;

// ---------------------------------------------------------------------------
// Scratch (__device__ globals; zero-initialized at load)
// ---------------------------------------------------------------------------
__device__ __align__(16) float g_h   [T_ * D_];
__device__ __align__(16) float g_qkv [T_ * QKVN];
__device__ __align__(16) float g_h1  [T_ * D_];
__device__ __align__(16) float g_part[2 * T_ * D_];   // split-K partials

__device__ __align__(16) fp16 g_hb_hi [T_ * D_];
__device__ __align__(16) fp16 g_hb_lo [T_ * D_];
__device__ __align__(16) fp16 g_ab_hi [T_ * D_];
__device__ __align__(16) fp16 g_ab_lo [T_ * D_];
__device__ __align__(16) fp16 g_h1b_hi[T_ * D_];
__device__ __align__(16) fp16 g_h1b_lo[T_ * D_];
__device__ __align__(16) fp16 g_tb_hi [T_ * F_];
__device__ __align__(16) fp16 g_tb_lo [T_ * F_];

// Prepped weights: W^T fp16 hi/lo, [N][K] K-major
__device__ __align__(16) fp16 g_wqkv_hi[L_ * QKVN * D_];
__device__ __align__(16) fp16 g_wqkv_lo[L_ * QKVN * D_];
__device__ __align__(16) fp16 g_wo_hi [L_ * D_ * D_];
__device__ __align__(16) fp16 g_wo_lo [L_ * D_ * D_];
__device__ __align__(16) fp16 g_w1_hi [L_ * D_ * F_];
__device__ __align__(16) fp16 g_w1_lo [L_ * D_ * F_];
__device__ __align__(16) fp16 g_w2_hi [L_ * D_ * F_];
__device__ __align__(16) fp16 g_w2_lo [L_ * D_ * F_];
__device__ __align__(16) fp16 g_wout_hi[VPAD * D_];   // pad rows stay zero
__device__ __align__(16) float g_bqkv[L_ * QKVN];

// ---------------------------------------------------------------------------
// Helpers
// ---------------------------------------------------------------------------
__device__ __forceinline__ float gelu_exact(float x) {
    return 0.5f * x * (1.0f + erff(x * 0.70710678118654752440f));
}
__device__ __forceinline__ uint32_t pack_h2(fp16 a, fp16 b) {
    return (uint32_t)__half_as_ushort(a) |
           ((uint32_t)__half_as_ushort(b) << 16);
}
__device__ __forceinline__ void split2(float x, fp16& h, fp16& l) {
    h = __float2half_rn(x);
    l = __float2half_rn(x - __half2float(h));
}
__device__ __forceinline__ float warp_sum(float v) {
    #pragma unroll
    for (int o = 16; o > 0; o >>= 1) v += __shfl_xor_sync(0xFFFFFFFFu, v, o);
    return v;
}
__device__ __forceinline__ uint32_t smem_u32(const void* p) {
    uint32_t a;
    asm("{ .reg .u64 t; cvta.to.shared.u64 t, %1; cvt.u32.u64 %0, t; }"
        : "=r"(a) : "l"(p));
    return a;
}
#define SWZ(off) ((off) ^ (((off) >> 3) & 0x70))

__device__ __forceinline__ void cpa16(uint32_t s, const void* g) {
    asm volatile("cp.async.cg.shared.global [%0], [%1], 16;" :: "r"(s), "l"(g));
}
#define CP_COMMIT() asm volatile("cp.async.commit_group;" ::: "memory")
#define CP_WAIT0()  asm volatile("cp.async.wait_group 0;" ::: "memory")

__device__ __forceinline__ void ldsm4(uint32_t (&r)[4], uint32_t addr) {
    asm volatile("ldmatrix.sync.aligned.m8n8.x4.shared.b16 {%0,%1,%2,%3}, [%4];"
        : "=r"(r[0]), "=r"(r[1]), "=r"(r[2]), "=r"(r[3]) : "r"(addr));
}
// fp16 inputs, fp32 accumulate (main product)
__device__ __forceinline__ void mma_f32(float* d, const uint32_t (&a)[4],
                                        uint32_t b0, uint32_t b1) {
    asm volatile("mma.sync.aligned.m16n8k16.row.col.f32.f16.f16.f32 "
        "{%0,%1,%2,%3}, {%4,%5,%6,%7}, {%8,%9}, {%0,%1,%2,%3};"
        : "+f"(d[0]), "+f"(d[1]), "+f"(d[2]), "+f"(d[3])
        : "r"(a[0]), "r"(a[1]), "r"(a[2]), "r"(a[3]), "r"(b0), "r"(b1));
}
// fp16 inputs, fp16 accumulate (correction products)
__device__ __forceinline__ void mma_f16(uint32_t (&d)[2], const uint32_t (&a)[4],
                                        uint32_t b0, uint32_t b1) {
    asm volatile("mma.sync.aligned.m16n8k16.row.col.f16.f16.f16.f16 "
        "{%0,%1}, {%2,%3,%4,%5}, {%6,%7}, {%0,%1};"
        : "+r"(d[0]), "+r"(d[1])
        : "r"(a[0]), "r"(a[1]), "r"(a[2]), "r"(a[3]), "r"(b0), "r"(b1));
}

// ---------------------------------------------------------------------------
// Weight prep: transpose + hi/lo split. in [K,N] -> out [N,K]
// olo may be null (skip lo plane; used for Wout whose GEMM is TERMS=1).
// ---------------------------------------------------------------------------
__global__ void __launch_bounds__(256) prep_w_kernel(
    const float* __restrict__ in, fp16* __restrict__ ohi, fp16* __restrict__ olo,
    int K, int N, long inBatch, int zdiv, long outL, long outZ)
{
    __shared__ float t[32][33];
    const int tx = threadIdx.x, ty = threadIdx.y;
    const int n0 = blockIdx.x * 32, k0 = blockIdx.y * 32;
    const int z = blockIdx.z;
    in += (long)z * inBatch;
    long ob = (long)(z / zdiv) * outL + (long)(z % zdiv) * outZ;
    ohi += ob;
    if (olo) olo += ob;
    #pragma unroll
    for (int i = 0; i < 4; i++)
        t[ty + i * 8][tx] = in[(long)(k0 + ty + i * 8) * N + n0 + tx];
    __syncthreads();
    #pragma unroll
    for (int i = 0; i < 4; i++) {
        float x = t[tx][ty + i * 8];
        fp16 hi, lo; split2(x, hi, lo);
        long o = (long)(n0 + ty + i * 8) * K + k0 + tx;
        ohi[o] = hi;
        if (olo) olo[o] = lo;
    }
}

// Merged QKV prep: one launch; z = src*(L*H) + l*H + head
__global__ void __launch_bounds__(256) prep_qkv_kernel(
    const float* __restrict__ Wq, const float* __restrict__ Wk,
    const float* __restrict__ Wv, fp16* __restrict__ ohi, fp16* __restrict__ olo)
{
    __shared__ float t[32][33];
    const int tx = threadIdx.x, ty = threadIdx.y;
    const int n0 = blockIdx.x * 32, k0 = blockIdx.y * 32;  // N=HD_, K=D_
    const int z = blockIdx.z;
    const int srcIdx = z / (L_ * H_);
    const int lh = z - srcIdx * (L_ * H_);
    const int l = lh / H_, head = lh - l * H_;
    const float* in = (srcIdx == 0 ? Wq : (srcIdx == 1 ? Wk : Wv))
                    + (long)lh * D_ * HD_;
    long ob = (long)l * QKVN * D_ + (long)srcIdx * D_ * D_ + (long)head * HD_ * D_;
    ohi += ob; olo += ob;
    #pragma unroll
    for (int i = 0; i < 4; i++)
        t[ty + i * 8][tx] = in[(long)(k0 + ty + i * 8) * HD_ + n0 + tx];
    __syncthreads();
    #pragma unroll
    for (int i = 0; i < 4; i++) {
        float x = t[tx][ty + i * 8];
        fp16 hi, lo; split2(x, hi, lo);
        long o = (long)(n0 + ty + i * 8) * D_ + k0 + tx;
        ohi[o] = hi; olo[o] = lo;
    }
}

__global__ void __launch_bounds__(256) concat_bias_kernel(
    const float* __restrict__ bq, const float* __restrict__ bk,
    const float* __restrict__ bv, float* __restrict__ out)
{
    int l = blockIdx.x;
    for (int i = threadIdx.x; i < D_; i += 256) {
        out[l * QKVN + i]           = bq[l * D_ + i];
        out[l * QKVN + D_ + i]      = bk[l * D_ + i];
        out[l * QKVN + 2 * D_ + i]  = bv[l * D_ + i];
    }
}

// ---------------------------------------------------------------------------
// HMMA GEMM: C[64, WN-tile] = A x W (+bias...). SPLITK: blockIdx.z picks a
// K-half; EPI=4 writes a raw fp32 partial plane (combine done downstream).
// WN=128: 8 warps 2x4, warp tile 32x32. WN=64: warp tile 32x16.
// TERMS=3: main ah*bh f32-acc + corrections (ah*bl + al*bh) in shared f16-acc.
// TERMS=1: main product only (terminal logits GEMM).
// K-chunk 64; double-buffered cp.async; 1 sync per chunk.
// EPI: 0 fp32 acc+bias ; 3 fp16 hi/lo of acc+bias ; 4 raw fp32 partial
// ---------------------------------------------------------------------------
#define MG_SMEM_N(WN) (2 * (16384 + 2 * (WN) * 128) + 1024)

template<int WN, int TERMS, int EPI, bool GUARD, int SPLITK>
__global__ void __launch_bounds__(256) mgemm_kernel(
    const fp16* __restrict__ Ahi, const fp16* __restrict__ Alo,
    const fp16* __restrict__ Bhi, const fp16* __restrict__ Blo,
    const float* __restrict__ bias,
    float* __restrict__ C, fp16* __restrict__ Chi, fp16* __restrict__ Clo,
    int K, int N)
{
    constexpr int NLD    = WN / 64;           // B ldsm4 per k-step
    constexpr int NT     = 2 * NLD;           // n8 tiles per warp
    constexpr int BB     = WN * 128;          // bytes per B plane
    constexpr int BSTEPS = WN / 32;           // B loader 32-row groups
    constexpr int STAGE  = 16384 + 2 * BB;

    extern __shared__ char dsm[];
    const uint32_t sraw  = smem_u32(dsm);
    const uint32_t sbase = (sraw + 1023u) & ~1023u;

    const int tid  = threadIdx.x;
    const int lane = tid & 31;
    const int wid  = tid >> 5;
    const int row0 = blockIdx.x * 64;
    const int col0 = blockIdx.y * WN;
    const int z    = (SPLITK > 1) ? blockIdx.z : 0;
    const int Klen = K / SPLITK;
    const int kOff = z * Klen;

    const int lrow = tid >> 3;
    const int lsub = tid & 7;
    const fp16* Ah0 = Ahi + (long)(row0 + lrow) * K + kOff + lsub * 8;
    const fp16* Al0 = (TERMS == 3) ? Alo + (long)(row0 + lrow) * K + kOff + lsub * 8 : nullptr;
    const fp16* Bh0 = Bhi + (long)(col0 + lrow) * K + kOff + lsub * 8;
    const fp16* Bl0 = (TERMS == 3) ? Blo + (long)(col0 + lrow) * K + kOff + lsub * 8 : nullptr;
    const uint32_t soff0 = SWZ((uint32_t)(lrow * 128 + lsub * 16));
    const long rstep = 32L * K;

#define LOAD_CHUNK(sb, ko) do {                                         \
        cpa16((sb) + soff0,                 Ah0 + (ko));                \
        cpa16((sb) + soff0 + 4096,          Ah0 + (ko) + rstep);        \
        if (TERMS == 3) {                                               \
            cpa16((sb) + 8192 + soff0,          Al0 + (ko));            \
            cpa16((sb) + 8192 + soff0 + 4096,   Al0 + (ko) + rstep);    \
        }                                                               \
        _Pragma("unroll")                                               \
        for (int jj = 0; jj < BSTEPS; jj++) {                           \
            cpa16((sb) + 16384 + soff0 + jj * 4096, Bh0 + (ko) + jj * rstep); \
            if (TERMS == 3)                                             \
                cpa16((sb) + 16384 + BB + soff0 + jj * 4096,            \
                      Bl0 + (ko) + jj * rstep);                         \
        }                                                               \
        CP_COMMIT();                                                    \
    } while (0)

    float acc[2][NT][4];
    #pragma unroll
    for (int i = 0; i < 2; i++)
        #pragma unroll
        for (int j = 0; j < NT; j++)
            #pragma unroll
            for (int c = 0; c < 4; c++) acc[i][j][c] = 0.f;
    uint32_t hacc[2][NT][2];
    #pragma unroll
    for (int i = 0; i < 2; i++)
        #pragma unroll
        for (int j = 0; j < NT; j++) { hacc[i][j][0] = 0u; hacc[i][j][1] = 0u; }

    const int m0w = (wid & 1) * 32;
    const int n0w = (wid >> 1) * (WN / 4);
    const uint32_t a_off0 = (uint32_t)((m0w + (lane & 15)) * 128 + ((lane >> 4) * 16));
    const uint32_t b_off0 = (uint32_t)((n0w + ((lane >> 4) * 8) + (lane & 7)) * 128
                                       + (((lane >> 3) & 1) * 16));

    const int nch = Klen / 64;

    LOAD_CHUNK(sbase, 0);

    for (int ch = 0; ch < nch; ch++) {
        CP_WAIT0();
        __syncthreads();
        if (ch + 1 < nch)
            LOAD_CHUNK(sbase + ((ch + 1) & 1) * STAGE, (ch + 1) * 64);

        const uint32_t sA = sbase + (ch & 1) * STAGE;
        const uint32_t sB = sA + 16384;

        #pragma unroll
        for (int ks = 0; ks < 4; ks++) {
            const uint32_t kb = ks * 32;
            uint32_t ah[2][4], bh[NLD][4];
            ldsm4(ah[0], sA + SWZ(a_off0 + kb));
            ldsm4(ah[1], sA + SWZ(a_off0 + 2048 + kb));
            #pragma unroll
            for (int np = 0; np < NLD; np++)
                ldsm4(bh[np], sB + SWZ(b_off0 + np * 2048 + kb));
            if (TERMS == 3) {
                uint32_t al[2][4], bl[NLD][4];
                ldsm4(al[0], sA + 8192 + SWZ(a_off0 + kb));
                ldsm4(al[1], sA + 8192 + SWZ(a_off0 + 2048 + kb));
                #pragma unroll
                for (int np = 0; np < NLD; np++)
                    ldsm4(bl[np], sB + BB + SWZ(b_off0 + np * 2048 + kb));
                #pragma unroll
                for (int mt = 0; mt < 2; mt++)
                    #pragma unroll
                    for (int np = 0; np < NLD; np++) {
                        mma_f32(acc[mt][2 * np],     ah[mt], bh[np][0], bh[np][1]);
                        mma_f32(acc[mt][2 * np + 1], ah[mt], bh[np][2], bh[np][3]);
                        mma_f16(hacc[mt][2 * np],     ah[mt], bl[np][0], bl[np][1]);
                        mma_f16(hacc[mt][2 * np + 1], ah[mt], bl[np][2], bl[np][3]);
                        mma_f16(hacc[mt][2 * np],     al[mt], bh[np][0], bh[np][1]);
                        mma_f16(hacc[mt][2 * np + 1], al[mt], bh[np][2], bh[np][3]);
                    }
            } else {
                #pragma unroll
                for (int mt = 0; mt < 2; mt++)
                    #pragma unroll
                    for (int np = 0; np < NLD; np++) {
                        mma_f32(acc[mt][2 * np],     ah[mt], bh[np][0], bh[np][1]);
                        mma_f32(acc[mt][2 * np + 1], ah[mt], bh[np][2], bh[np][3]);
                    }
            }
        }
    }
#undef LOAD_CHUNK

    // Fold fp16 correction accumulators into fp32 acc
    if (TERMS == 3) {
        #pragma unroll
        for (int mt = 0; mt < 2; mt++)
            #pragma unroll
            for (int nt = 0; nt < NT; nt++) {
                float2 c0 = __half22float2(*(const __half2*)&hacc[mt][nt][0]);
                float2 c1 = __half22float2(*(const __half2*)&hacc[mt][nt][1]);
                acc[mt][nt][0] += c0.x; acc[mt][nt][1] += c0.y;
                acc[mt][nt][2] += c1.x; acc[mt][nt][3] += c1.y;
            }
    }

    // Epilogue
    float* Cz = (EPI == 4) ? C + (long)z * ((long)T_ * N) : C;
    #pragma unroll
    for (int mt = 0; mt < 2; mt++) {
        const int r0 = row0 + m0w + mt * 16 + (lane >> 2);
        #pragma unroll
        for (int nt = 0; nt < NT; nt++) {
            const int col = col0 + n0w + nt * 8 + (lane & 3) * 2;
            if (GUARD && col >= N) continue;
            const float* a4 = acc[mt][nt];
            const long off0 = (long)r0 * N + col;
            const long off1 = (long)(r0 + 8) * N + col;
            if (EPI == 4) {
                *(float2*)(Cz + off0) = make_float2(a4[0], a4[1]);
                *(float2*)(Cz + off1) = make_float2(a4[2], a4[3]);
            } else {
                float2 bv = *(const float2*)(bias + col);
                float o0x = a4[0] + bv.x, o0y = a4[1] + bv.y;
                float o1x = a4[2] + bv.x, o1y = a4[3] + bv.y;
                if (EPI == 3) {
                    fp16 h0, l0, h1, l1;
                    split2(o0x, h0, l0); split2(o0y, h1, l1);
                    *(uint32_t*)(Chi + off0) = pack_h2(h0, h1);
                    *(uint32_t*)(Clo + off0) = pack_h2(l0, l1);
                    split2(o1x, h0, l0); split2(o1y, h1, l1);
                    *(uint32_t*)(Chi + off1) = pack_h2(h0, h1);
                    *(uint32_t*)(Clo + off1) = pack_h2(l0, l1);
                } else {
                    *(float2*)(C + off0) = make_float2(o0x, o0y);
                    *(float2*)(C + off1) = make_float2(o1x, o1y);
                }
            }
        }
    }
}

// ---------------------------------------------------------------------------
// Embedding: h fp32 + hi/lo fp16
// ---------------------------------------------------------------------------
__global__ void __launch_bounds__(256) embed_kernel(
    const int* __restrict__ x, const float* __restrict__ bpe,
    const float* __restrict__ pe, float* __restrict__ h,
    fp16* __restrict__ hbh, fp16* __restrict__ hbl)
{
    int t = blockIdx.x;
    int s = t & (S_ - 1);
    long tok = x[t];
    const float* bp = bpe + tok * (long)D_;
    const float* pp = pe + (long)s * D_;
    long rb = (long)t * D_;
    #pragma unroll
    for (int i = 0; i < 3; i++) {
        int c = threadIdx.x + i * 256;
        float v = bp[c] + pp[c];
        h[rb + c] = v;
        fp16 hi, lo; split2(v, hi, lo);
        hbh[rb + c] = hi; hbl[rb + c] = lo;
    }
}

// ---------------------------------------------------------------------------
// Attention v2: one block per (b,h), 256 threads, ~101KB smem.
// ---------------------------------------------------------------------------
#define ATTN_SMEM ((128 * 64 + 128 * 129 + 512) * 4)

__global__ void __launch_bounds__(256) attn_kernel(
    const float* __restrict__ qkv, const int* __restrict__ ignore,
    fp16* __restrict__ ohi, fp16* __restrict__ olo)
{
    extern __shared__ float sm[];
    float* KV   = sm;                        // [128][64]
    float* P    = sm + 128 * 64;             // [128][129]
    float* redm = sm + 128 * 64 + 128 * 129; // [2][128]
    float* reds = redm + 256;                // [2][128]
    __shared__ int ig[S_];

    const int bh = blockIdx.x;
    const int b  = bh / H_;
    const int h  = bh % H_;
    const int tid  = threadIdx.x;
    const int q    = tid & 127;
    const int half = tid >> 7;
    const long qbase = (long)b * S_ * QKVN + (long)h * HD_;
    const long kbase = qbase + D_;
    const long vbase = qbase + 2 * D_;

    if (tid < S_) ig[tid] = ignore[b * S_ + tid];

    #pragma unroll
    for (int i = 0; i < 8; i++) {
        int idx = tid + i * 256;
        int row = idx >> 4;
        int c4  = idx & 15;
        *(float4*)&KV[row * 64 + c4 * 4] =
            *(const float4*)(qkv + kbase + (long)row * QKVN + c4 * 4);
    }
    float qr[64];
    #pragma unroll
    for (int i = 0; i < 16; i++)
        *(float4*)&qr[i * 4] = *(const float4*)(qkv + qbase + (long)q * QKVN + i * 4);
    __syncthreads();

    float mx = -FLT_MAX;
    const int k0 = half * 64;
    for (int kk = k0; kk < k0 + 64; kk++) {
        float s = 0.f;
        #pragma unroll
        for (int e = 0; e < 64; e += 4) {
            float4 kv = *(const float4*)&KV[kk * 64 + e];
            s = fmaf(qr[e + 0], kv.x, s);
            s = fmaf(qr[e + 1], kv.y, s);
            s = fmaf(qr[e + 2], kv.z, s);
            s = fmaf(qr[e + 3], kv.w, s);
        }
        bool allowed = (kk <= q) && (ig[kk] == 0 || kk == q);
        float val = allowed ? s * 0.125f : -FLT_MAX;
        P[q * 129 + kk] = val;
        mx = fmaxf(mx, val);
    }
    redm[half * 128 + q] = mx;
    __syncthreads();

    mx = fmaxf(redm[q], redm[128 + q]);

    #pragma unroll
    for (int i = 0; i < 8; i++) {
        int idx = tid + i * 256;
        int row = idx >> 4;
        int c4  = idx & 15;
        *(float4*)&KV[row * 64 + c4 * 4] =
            *(const float4*)(qkv + vbase + (long)row * QKVN + c4 * 4);
    }
    float sum = 0.f;
    for (int kk = k0; kk < k0 + 64; kk++) {
        float e = expf(P[q * 129 + kk] - mx);
        P[q * 129 + kk] = e;
        sum += e;
    }
    reds[half * 128 + q] = sum;
    __syncthreads();

    const float inv = 1.0f / (reds[q] + reds[128 + q]);

    const int d0 = half * 32;
    float acc[32] = {};
    for (int kk = 0; kk < S_; kk++) {
        float p = P[q * 129 + kk];
        #pragma unroll
        for (int e = 0; e < 32; e += 4) {
            float4 vv = *(const float4*)&KV[kk * 64 + d0 + e];
            acc[e + 0] = fmaf(p, vv.x, acc[e + 0]);
            acc[e + 1] = fmaf(p, vv.y, acc[e + 1]);
            acc[e + 2] = fmaf(p, vv.z, acc[e + 2]);
            acc[e + 3] = fmaf(p, vv.w, acc[e + 3]);
        }
    }
    const long obase = (long)(b * S_ + q) * D_ + (long)h * HD_ + d0;
    #pragma unroll
    for (int i = 0; i < 16; i++) {
        float v0 = acc[i * 2] * inv, v1 = acc[i * 2 + 1] * inv;
        fp16 h0, l0, h1, l1;
        split2(v0, h0, l0); split2(v1, h1, l1);
        *(uint32_t*)(ohi + obase + i * 2) = pack_h2(h0, h1);
        *(uint32_t*)(olo + obase + i * 2) = pack_h2(l0, l1);
    }
}

// ---------------------------------------------------------------------------
// Combine + LayerNorm: warp-per-row, no block barriers. 8 rows/block.
// v = res + [gelu](p0 + p1 + bias); out = LN(v) (fp32 + fp16 hi/lo).
// ---------------------------------------------------------------------------
template<bool GELU>
__global__ void __launch_bounds__(256) ln_comb_kernel(
    const float* __restrict__ res, const float* __restrict__ part,
    const float* __restrict__ bias, const float* __restrict__ w,
    const float* __restrict__ b, float* __restrict__ out,
    fp16* __restrict__ obh, fp16* __restrict__ obl)
{
    const int wrp  = threadIdx.x >> 5;
    const int lane = threadIdx.x & 31;
    const int row  = blockIdx.x * 8 + wrp;
    const long rb  = (long)row * D_;
    const float* p0 = part + rb;
    const float* p1 = part + (long)T_ * D_ + rb;
    const float* rr = res + rb;

    float v[24];
    float s = 0.f, s2 = 0.f;
    #pragma unroll
    for (int i = 0; i < 6; i++) {
        const int c = lane * 4 + i * 128;
        float4 r4 = *(const float4*)(rr + c);
        float4 a4 = *(const float4*)(p0 + c);
        float4 q4 = *(const float4*)(p1 + c);
        float4 b4 = *(const float4*)(bias + c);
        float t0 = a4.x + q4.x + b4.x;
        float t1 = a4.y + q4.y + b4.y;
        float t2 = a4.z + q4.z + b4.z;
        float t3 = a4.w + q4.w + b4.w;
        float x0, x1, x2, x3;
        if (GELU) {
            x0 = r4.x + gelu_exact(t0); x1 = r4.y + gelu_exact(t1);
            x2 = r4.z + gelu_exact(t2); x3 = r4.w + gelu_exact(t3);
        } else {
            x0 = r4.x + t0; x1 = r4.y + t1;
            x2 = r4.z + t2; x3 = r4.w + t3;
        }
        v[i * 4 + 0] = x0; v[i * 4 + 1] = x1;
        v[i * 4 + 2] = x2; v[i * 4 + 3] = x3;
        s += x0 + x1 + x2 + x3;
        s2 = fmaf(x0, x0, s2); s2 = fmaf(x1, x1, s2);
        s2 = fmaf(x2, x2, s2); s2 = fmaf(x3, x3, s2);
    }
    s  = warp_sum(s);
    s2 = warp_sum(s2);
    const float mu  = s * (1.0f / D_);
    const float var = s2 * (1.0f / D_) - mu * mu;
    const float rs  = rsqrtf(var + 1e-5f);

    #pragma unroll
    for (int i = 0; i < 6; i++) {
        const int c = lane * 4 + i * 128;
        float4 w4 = *(const float4*)(w + c);
        float4 b4 = *(const float4*)(b + c);
        float4 o;
        o.x = (v[i * 4 + 0] - mu) * rs * w4.x + b4.x;
        o.y = (v[i * 4 + 1] - mu) * rs * w4.y + b4.y;
        o.z = (v[i * 4 + 2] - mu) * rs * w4.z + b4.z;
        o.w = (v[i * 4 + 3] - mu) * rs * w4.w + b4.w;
        *(float4*)(out + rb + c) = o;
        fp16 h0, l0, h1, l1, h2, l2, h3, l3;
        split2(o.x, h0, l0); split2(o.y, h1, l1);
        split2(o.z, h2, l2); split2(o.w, h3, l3);
        *(uint2*)(obh + rb + c) = make_uint2(pack_h2(h0, h1), pack_h2(h2, h3));
        *(uint2*)(obl + rb + c) = make_uint2(pack_h2(l0, l1), pack_h2(l2, l3));
    }
}

// ---------------------------------------------------------------------------
// Launch
// ---------------------------------------------------------------------------
extern "C" void kernel_launch(void* const* d_in, const int* in_sizes, int n_in,
                              void* d_out, int out_size)
{
    const int*   x      = (const int*)  d_in[0];
    const int*   ignore = (const int*)  d_in[1];
    const float* bpe    = (const float*)d_in[2];
    const float* pe     = (const float*)d_in[3];
    const float* Wq     = (const float*)d_in[4];
    const float* bq     = (const float*)d_in[5];
    const float* Wk     = (const float*)d_in[6];
    const float* bk     = (const float*)d_in[7];
    const float* Wv     = (const float*)d_in[8];
    const float* bv     = (const float*)d_in[9];
    const float* Wo     = (const float*)d_in[10];
    const float* bo     = (const float*)d_in[11];
    const float* W1     = (const float*)d_in[12];
    const float* b1     = (const float*)d_in[13];
    const float* W2     = (const float*)d_in[14];
    const float* b2     = (const float*)d_in[15];
    const float* ln1w   = (const float*)d_in[16];
    const float* ln1b   = (const float*)d_in[17];
    const float* ln2w   = (const float*)d_in[18];
    const float* ln2b   = (const float*)d_in[19];
    const float* Wout   = (const float*)d_in[20];
    const float* bout   = (const float*)d_in[21];
    float* out = (float*)d_out;

    // Side stream + events for prep overlap (created once; graph capture
    // records them as fork/join dependencies each capture).
    static cudaStream_t s2 = nullptr;
    static cudaEvent_t evFork = nullptr, evJoin = nullptr;
    if (!s2) {
        cudaStreamCreateWithFlags(&s2, cudaStreamNonBlocking);
        cudaEventCreateWithFlags(&evFork, cudaEventDisableTiming);
        cudaEventCreateWithFlags(&evJoin, cudaEventDisableTiming);
    }

    cudaFuncSetAttribute(attn_kernel,
        cudaFuncAttributeMaxDynamicSharedMemorySize, ATTN_SMEM);
    cudaFuncSetAttribute(mgemm_kernel<128, 3, 0, false, 1>,
        cudaFuncAttributeMaxDynamicSharedMemorySize, MG_SMEM_N(128));
    cudaFuncSetAttribute(mgemm_kernel<128, 3, 3, false, 1>,
        cudaFuncAttributeMaxDynamicSharedMemorySize, MG_SMEM_N(128));
    cudaFuncSetAttribute(mgemm_kernel<64, 3, 4, false, 2>,
        cudaFuncAttributeMaxDynamicSharedMemorySize, MG_SMEM_N(64));
    cudaFuncSetAttribute(mgemm_kernel<128, 1, 0, true, 1>,
        cudaFuncAttributeMaxDynamicSharedMemorySize, MG_SMEM_N(128));

    float *h, *qkv, *h1, *part, *bqkv;
    fp16 *hbh, *hbl, *abh, *abl, *h1bh, *h1bl, *tbh, *tbl;
    fp16 *wqkvh, *wqkvl, *woh, *wol, *w1h, *w1l, *w2h, *w2l, *wouth;
    cudaGetSymbolAddress((void**)&h,    g_h);
    cudaGetSymbolAddress((void**)&qkv,  g_qkv);
    cudaGetSymbolAddress((void**)&h1,   g_h1);
    cudaGetSymbolAddress((void**)&part, g_part);
    cudaGetSymbolAddress((void**)&hbh,  g_hb_hi);
    cudaGetSymbolAddress((void**)&hbl,  g_hb_lo);
    cudaGetSymbolAddress((void**)&abh,  g_ab_hi);
    cudaGetSymbolAddress((void**)&abl,  g_ab_lo);
    cudaGetSymbolAddress((void**)&h1bh, g_h1b_hi);
    cudaGetSymbolAddress((void**)&h1bl, g_h1b_lo);
    cudaGetSymbolAddress((void**)&tbh,  g_tb_hi);
    cudaGetSymbolAddress((void**)&tbl,  g_tb_lo);
    cudaGetSymbolAddress((void**)&wqkvh, g_wqkv_hi);
    cudaGetSymbolAddress((void**)&wqkvl, g_wqkv_lo);
    cudaGetSymbolAddress((void**)&woh,  g_wo_hi);
    cudaGetSymbolAddress((void**)&wol,  g_wo_lo);
    cudaGetSymbolAddress((void**)&w1h,  g_w1_hi);
    cudaGetSymbolAddress((void**)&w1l,  g_w1_lo);
    cudaGetSymbolAddress((void**)&w2h,  g_w2_hi);
    cudaGetSymbolAddress((void**)&w2l,  g_w2_lo);
    cudaGetSymbolAddress((void**)&wouth, g_wout_hi);
    cudaGetSymbolAddress((void**)&bqkv, g_bqkv);

    const dim3 gQKV(T_ / 64, QKVN / 128);      // 32 x 18
    const dim3 gDsp(T_ / 64, D_ / 64, 2);      // 32 x 12 x 2 (split-K)
    const dim3 gF  (T_ / 64, F_ / 128);        // 32 x 24
    const dim3 gV  (T_ / 64, VPAD / 128);      // 32 x 313

    dim3 pb(32, 8);
    // Main stream: QKV prep chain (needed immediately).
    prep_qkv_kernel<<<dim3(2, 24, 3 * L_ * H_), pb>>>(Wq, Wk, Wv, wqkvh, wqkvl);
    concat_bias_kernel<<<L_, 256>>>(bq, bk, bv, bqkv);
    embed_kernel<<<T_, 256>>>(x, bpe, pe, h, hbh, hbl);

    // Fork: remaining weight preps run on s2, overlapping QKV GEMM + attention.
    cudaEventRecord(evFork, 0);
    cudaStreamWaitEvent(s2, evFork, 0);
    prep_w_kernel<<<dim3(24, 24, L_), pb, 0, s2>>>(Wo, woh, wol,
        D_, D_, (long)D_ * D_, 1, (long)D_ * D_, 0);
    prep_w_kernel<<<dim3(96, 24, L_), pb, 0, s2>>>(W1, w1h, w1l,
        D_, F_, (long)D_ * F_, 1, (long)D_ * F_, 0);
    prep_w_kernel<<<dim3(24, 96, L_), pb, 0, s2>>>(W2, w2h, w2l,
        F_, D_, (long)F_ * D_, 1, (long)F_ * D_, 0);
    prep_w_kernel<<<dim3(1250, 24, 1), pb, 0, s2>>>(Wout, wouth, nullptr,
        D_, V_, 0, 1, 0, 0);
    cudaEventRecord(evJoin, s2);

    // Layer-0 QKV GEMM + attention run concurrently with the preps.
    mgemm_kernel<128, 3, 0, false, 1><<<gQKV, 256, MG_SMEM_N(128)>>>(
        hbh, hbl, wqkvh, wqkvl, bqkv, qkv, nullptr, nullptr, D_, QKVN);
    attn_kernel<<<B_ * H_, 256, ATTN_SMEM>>>(qkv, ignore, abh, abl);

    // Join: Wo/W1/W2/Wout planes must be ready from here on.
    cudaStreamWaitEvent(0, evJoin, 0);

    for (int l = 0; l < L_; l++) {
        long wq_off = (long)l * QKVN * D_;
        long wd_off = (long)l * D_ * D_;
        long wf_off = (long)l * D_ * F_;

        if (l > 0) {
            mgemm_kernel<128, 3, 0, false, 1><<<gQKV, 256, MG_SMEM_N(128)>>>(
                hbh, hbl, wqkvh + wq_off, wqkvl + wq_off, bqkv + (long)l * QKVN,
                qkv, nullptr, nullptr, D_, QKVN);
            attn_kernel<<<B_ * H_, 256, ATTN_SMEM>>>(qkv, ignore, abh, abl);
        }

        // partials = a @ Wo (split-K=2)
        mgemm_kernel<64, 3, 4, false, 2><<<gDsp, 256, MG_SMEM_N(64)>>>(
            abh, abl, woh + wd_off, wol + wd_off, nullptr,
            part, nullptr, nullptr, D_, D_);
        // h1 = LN1(h + p0 + p1 + bo)
        ln_comb_kernel<false><<<T_ / 8, 256>>>(h, part, bo + (long)l * D_,
            ln1w + (long)l * D_, ln1b + (long)l * D_, h1, h1bh, h1bl);
        // t = h1 @ W1 + b1 (fp16-only output)
        mgemm_kernel<128, 3, 3, false, 1><<<gF, 256, MG_SMEM_N(128)>>>(
            h1bh, h1bl, w1h + wf_off, w1l + wf_off, b1 + (long)l * F_,
            nullptr, tbh, tbl, D_, F_);
        // partials = t @ W2 (split-K=2 over K=3072)
        mgemm_kernel<64, 3, 4, false, 2><<<gDsp, 256, MG_SMEM_N(64)>>>(
            tbh, tbl, w2h + wf_off, w2l + wf_off, nullptr,
            part, nullptr, nullptr, F_, D_);
        // h = LN2(h1 + gelu(p0 + p1 + b2))
        ln_comb_kernel<true><<<T_ / 8, 256>>>(h1, part, b2 + (long)l * D_,
            ln2w + (long)l * D_, ln2b + (long)l * D_, h, hbh, hbl);
    }

    // logits = h @ Wout + bout (terminal GEMM: main term only, hi plane only)
    mgemm_kernel<128, 1, 0, true, 1><<<gV, 256, MG_SMEM_N(128)>>>(
        hbh, hbl, wouth, nullptr, bout, out, nullptr, nullptr, D_, V_);
}